// round 12
// baseline (speedup 1.0000x reference)
#include <cuda_runtime.h>
#include <cuda_fp16.h>
#include <stdint.h>
#include <math.h>

// Problem dims
#define Bb   16
#define Ss   512
#define Dd   768
#define Hh   8
#define Vv   100
#define Ff   2048
#define Ll   6
#define DHd  96
#define Mm   (Bb*Ss)   // 8192
#define QKVS (3*Dd)    // 2304

// ================= low-level helpers =================
__device__ __forceinline__ uint32_t smem_u32(const void* p) {
    return (uint32_t)__cvta_generic_to_shared(p);
}
__device__ __forceinline__ void cp_async16(uint32_t dst, const void* src, int szvalid) {
    asm volatile("cp.async.cg.shared.global [%0], [%1], 16, %2;"
                 :: "r"(dst), "l"(src), "r"(szvalid) : "memory");
}
#define CP_COMMIT() asm volatile("cp.async.commit_group;" ::: "memory")
#define CP_WAIT(n)  asm volatile("cp.async.wait_group %0;" :: "n"(n) : "memory")

__device__ __forceinline__ void ldm_x4(uint32_t* r, uint32_t addr) {
    asm volatile("ldmatrix.sync.aligned.m8n8.x4.shared.b16 {%0,%1,%2,%3}, [%4];"
                 : "=r"(r[0]), "=r"(r[1]), "=r"(r[2]), "=r"(r[3]) : "r"(addr));
}
__device__ __forceinline__ void ldm_trans_x4(uint32_t* r, uint32_t addr) {
    asm volatile("ldmatrix.sync.aligned.m8n8.x4.trans.shared.b16 {%0,%1,%2,%3}, [%4];"
                 : "=r"(r[0]), "=r"(r[1]), "=r"(r[2]), "=r"(r[3]) : "r"(addr));
}
__device__ __forceinline__ void mma16816(float* d, const uint32_t* a, const uint32_t* b) {
    asm volatile("mma.sync.aligned.m16n8k16.row.col.f32.f16.f16.f32 "
                 "{%0,%1,%2,%3}, {%4,%5,%6,%7}, {%8,%9}, {%0,%1,%2,%3};"
                 : "+f"(d[0]), "+f"(d[1]), "+f"(d[2]), "+f"(d[3])
                 : "r"(a[0]), "r"(a[1]), "r"(a[2]), "r"(a[3]), "r"(b[0]), "r"(b[1]));
}
__device__ __forceinline__ uint32_t pack_h2(float a, float b) {
    __half2 t = __floats2half2_rn(a, b);
    return *(uint32_t*)&t;
}
__device__ __forceinline__ float ex2(float x) {
    float y;
    asm("ex2.approx.f32 %0, %1;" : "=f"(y) : "f"(x));
    return y;
}

// ================= device scratch =================
__device__ float g_x   [Mm * Dd];
__device__ float g_cat [Ll * Bb * Dd];
__device__ float g_ca  [Ll * Bb * Dd];

__device__ __align__(16) __half g_x16 [Mm * Dd];
__device__ __align__(16) __half g_o16 [Mm * Dd];
__device__ __align__(16) __half g_y16 [Mm * Dd];
__device__ __align__(16) __half g_h16 [Mm * Ff];
__device__ __align__(16) __half g_qkv16[Mm * QKVS];

__device__ __align__(16) __half g_wqkv16[Ll*3*Dd*Dd];
__device__ __align__(16) __half g_wo16  [Ll*Dd*Dd];
__device__ __align__(16) __half g_w116  [Ll*Ff*Dd];
__device__ __align__(16) __half g_w216  [Ll*Dd*Ff];
__device__ __align__(16) __half g_wout16[Vv*Dd];

// ================= weight convert =================
__global__ __launch_bounds__(256) void convert_all(
    const float* __restrict__ s0, __half* __restrict__ d0, int b0,
    const float* __restrict__ s1, __half* __restrict__ d1, int b1,
    const float* __restrict__ s2, __half* __restrict__ d2, int b2,
    const float* __restrict__ s3, __half* __restrict__ d3, int b3,
    const float* __restrict__ s4, __half* __restrict__ d4, int b4)
{
    int bid = blockIdx.x;
    const float* src; __half* dst; int nb;
    if      (bid < b0)          { src = s0; dst = d0; nb = bid; }
    else if (bid < b0+b1)       { src = s1; dst = d1; nb = bid - b0; }
    else if (bid < b0+b1+b2)    { src = s2; dst = d2; nb = bid - b0 - b1; }
    else if (bid < b0+b1+b2+b3) { src = s3; dst = d3; nb = bid - b0 - b1 - b2; }
    else                        { src = s4; dst = d4; nb = bid - b0 - b1 - b2 - b3; }
    int i = (nb * 256 + threadIdx.x) * 4;
    float4 v = *(const float4*)&src[i];
    *(__half2*)&dst[i]     = __floats2half2_rn(v.x, v.y);
    *(__half2*)&dst[i + 2] = __floats2half2_rn(v.z, v.w);
}

// ================= embed =================
__global__ __launch_bounds__(256) void embed_kernel(
    const int* __restrict__ target, const float* __restrict__ tok,
    const float* __restrict__ pos, float* __restrict__ x,
    __half* __restrict__ x16)
{
    int row = blockIdx.x;
    int s   = row & (Ss - 1);
    int t   = target[row];
    const float* tp = tok + (size_t)t * Dd;
    const float* pp = pos + (size_t)s * Dd;
    size_t base = (size_t)row * Dd;
    for (int c = threadIdx.x; c < Dd; c += 256) {
        float v = tp[c] + pp[c];
        x[base + c] = v;
        x16[base + c] = __float2half(v);
    }
}

// ================= fp16 GEMM: CTA 128x128, 4 warps, 3-stage (FROZEN) =========
#define BKc 32
#define APITCH 80
#define T128_B   (128*APITCH)
#define STAGE_B  (2*T128_B)
#define GEMM_SMEM (3*STAGE_B)

__global__ void __launch_bounds__(128, 3) gemm_fp16(
    const __half* __restrict__ A, const __half* __restrict__ W,
    const float* __restrict__ bias, float* __restrict__ C,
    __half* __restrict__ Ch,
    int M, int N, int K, int mode)
{
    extern __shared__ char sm[];
    const uint32_t smU = smem_u32(sm);
    const int tid  = threadIdx.x;
    const int lane = tid & 31;
    const int wid  = tid >> 5;
    const int bm   = blockIdx.y * 128;
    const int bn   = blockIdx.x * 128;
    const int wm   = (wid >> 1) * 64;
    const int wn   = (wid & 1) * 64;

    float acc[4][8][4];
    #pragma unroll
    for (int i = 0; i < 4; ++i)
        #pragma unroll
        for (int j = 0; j < 8; ++j)
            #pragma unroll
            for (int r = 0; r < 4; ++r) acc[i][j][r] = 0.f;

    const int NC = K / BKc;

    auto issue = [&](int chunk, int s) {
        const int k0 = chunk * BKc;
        #pragma unroll
        for (int i = 0; i < 4; ++i) {
            int c = tid + 128 * i;
            int row = c >> 2, c16 = c & 3;
            cp_async16(smU + s * STAGE_B + row * APITCH + c16 * 16,
                       (const char*)(A + (size_t)(bm + row) * K + k0) + c16 * 16, 16);
        }
        #pragma unroll
        for (int i = 0; i < 4; ++i) {
            int c = tid + 128 * i;
            int row = c >> 2, c16 = c & 3;
            int rn = bn + row;
            const char* g = (const char*)(W + (size_t)rn * K + k0) + c16 * 16;
            int sz = 16;
            if (rn >= N) { sz = 0; g = (const char*)W; }
            cp_async16(smU + s * STAGE_B + T128_B + row * APITCH + c16 * 16, g, sz);
        }
        CP_COMMIT();
    };

    const int wrow_off = ((lane >> 4) << 3) + (lane & 7);
    const int wcol_off = ((lane >> 3) & 1) * 8;
    const int arow_off = lane & 15;
    const int acol_off = (lane >> 4) << 3;

    auto compute = [&](int s) {
        const uint32_t aB = smU + s * STAGE_B;
        const uint32_t wB = aB + T128_B;
        #pragma unroll
        for (int ks = 0; ks < BKc; ks += 16) {
            uint32_t wh[4][4];
            #pragma unroll
            for (int nb = 0; nb < 4; ++nb)
                ldm_x4(wh[nb], wB + (wn + nb * 16 + wrow_off) * APITCH + (ks + wcol_off) * 2);
            #pragma unroll
            for (int mi = 0; mi < 4; ++mi) {
                uint32_t ah[4];
                ldm_x4(ah, aB + (wm + mi * 16 + arow_off) * APITCH + (ks + acol_off) * 2);
                #pragma unroll
                for (int nb = 0; nb < 4; ++nb) {
                    mma16816(&acc[mi][nb * 2][0],     ah, &wh[nb][0]);
                    mma16816(&acc[mi][nb * 2 + 1][0], ah, &wh[nb][2]);
                }
            }
        }
    };

    issue(0, 0);
    issue(1, 1);
    for (int c = 0; c < NC; ++c) {
        if (c + 1 < NC) { CP_WAIT(1); } else { CP_WAIT(0); }
        __syncthreads();
        if (c + 2 < NC) issue(c + 2, (c + 2) % 3);
        compute(c % 3);
    }

    float bs[16];
    #pragma unroll
    for (int nj = 0; nj < 8; ++nj) {
        int c0 = bn + wn + nj * 8 + (lane & 3) * 2;
        bs[nj * 2]     = (c0 < N)     ? bias[c0]     : 0.f;
        bs[nj * 2 + 1] = (c0 + 1 < N) ? bias[c0 + 1] : 0.f;
    }
    #pragma unroll
    for (int mi = 0; mi < 4; ++mi) {
        #pragma unroll
        for (int nj = 0; nj < 8; ++nj) {
            int c0 = bn + wn + nj * 8 + (lane & 3) * 2;
            if (c0 >= N) continue;
            #pragma unroll
            for (int p = 0; p < 2; ++p) {
                int row = bm + wm + mi * 16 + (lane >> 2) + p * 8;
                float v0 = acc[mi][nj][p * 2]     + bs[nj * 2];
                float v1 = acc[mi][nj][p * 2 + 1] + bs[nj * 2 + 1];
                if (mode == 0) {
                    *(float2*)(C + (size_t)row * N + c0) = make_float2(v0, v1);
                } else {
                    if (mode == 1) { v0 = fmaxf(v0, 0.f); v1 = fmaxf(v1, 0.f); }
                    *(__half2*)(Ch + (size_t)row * N + c0) = __floats2half2_rn(v0, v1);
                }
            }
        }
    }
}

// ================= batched tiny GEMM (all layers in one launch) =================
__global__ __launch_bounds__(256) void small_gemm_all(
    const float* __restrict__ A, int aStrideL,
    const float* __restrict__ W, size_t wStrideL,
    const float* __restrict__ bias, int biasStrideL,
    float* __restrict__ C)
{
    int wg   = blockIdx.x * 8 + (threadIdx.x >> 5);
    int lane = threadIdx.x & 31;
    if (wg >= Ll * Bb * Dd) return;
    int l  = wg / (Bb * Dd);
    int r  = wg - l * (Bb * Dd);
    int bq = r / Dd;
    int n  = r - bq * Dd;
    const float* a = A + (size_t)l * aStrideL + (size_t)bq * Dd;
    const float* w = W + (size_t)l * wStrideL + (size_t)n * Dd;
    float s = 0.f;
    #pragma unroll 4
    for (int k = lane; k < Dd; k += 32) s = fmaf(a[k], w[k], s);
    #pragma unroll
    for (int o = 16; o; o >>= 1) s += __shfl_xor_sync(0xffffffffu, s, o);
    if (lane == 0) C[wg] = s + bias[(size_t)l * biasStrideL + n];
}

// ================= add+LN (ln3): 2 rows per 256-thread block =================
__global__ __launch_bounds__(256) void add_ln_kernel(
    float* __restrict__ x, const __half* __restrict__ y16,
    const float* __restrict__ g, const float* __restrict__ b,
    __half* __restrict__ x16)
{
    const int tid = threadIdx.x;
    const int grp = tid >> 7;
    const int t   = tid & 127;
    const int row = blockIdx.x * 2 + grp;
    const __half* yp = y16 + (size_t)row * Dd;
    float* xp = x + (size_t)row * Dd;
    __shared__ float sh1[2][4], sh2[2][4];
    const int w4   = (tid >> 5) & 3;
    const int lane = tid & 31;

    float v[6];
    float sum = 0.f, sq = 0.f;
    #pragma unroll
    for (int i = 0; i < 6; ++i) {
        int c = t + i * 128;
        float tt = xp[c] + __half2float(yp[c]);
        v[i] = tt; sum += tt; sq = fmaf(tt, tt, sq);
    }
    #pragma unroll
    for (int o = 16; o; o >>= 1) {
        sum += __shfl_xor_sync(0xffffffffu, sum, o);
        sq  += __shfl_xor_sync(0xffffffffu, sq,  o);
    }
    if (lane == 0) { sh1[grp][w4] = sum; sh2[grp][w4] = sq; }
    __syncthreads();
    if (t == 0) {
        float a = 0.f, c2 = 0.f;
        #pragma unroll
        for (int i = 0; i < 4; ++i) { a += sh1[grp][i]; c2 += sh2[grp][i]; }
        sh1[grp][0] = a; sh2[grp][0] = c2;
    }
    __syncthreads();
    float mu  = sh1[grp][0] * (1.f / Dd);
    float var = sh2[grp][0] * (1.f / Dd) - mu * mu;
    float rs  = rsqrtf(var + 1e-5f);
    #pragma unroll
    for (int i = 0; i < 6; ++i) {
        int c = t + i * 128;
        float o = (v[i] - mu) * rs * g[c] + b[c];
        xp[c] = o;
        x16[(size_t)row * Dd + c] = __float2half(o);
    }
}

// ================= fused (add+LN1)+(add bcast+LN2): 2 rows per block ===========
__global__ __launch_bounds__(256) void add_ln2_kernel(
    float* __restrict__ x, const __half* __restrict__ y16,
    const float* __restrict__ ca,
    const float* __restrict__ g1, const float* __restrict__ b1,
    const float* __restrict__ g2, const float* __restrict__ b2,
    __half* __restrict__ x16)
{
    const int tid = threadIdx.x;
    const int grp = tid >> 7;
    const int t   = tid & 127;
    const int row = blockIdx.x * 2 + grp;
    const __half* yp  = y16 + (size_t)row * Dd;
    const float* cap  = ca  + (size_t)(row >> 9) * Dd;
    float* xp = x + (size_t)row * Dd;
    __shared__ float sh1[2][4], sh2[2][4];
    const int w4   = (tid >> 5) & 3;
    const int lane = tid & 31;

    float v[6];
    float sum = 0.f, sq = 0.f;
    #pragma unroll
    for (int i = 0; i < 6; ++i) {
        int c = t + i * 128;
        float tt = xp[c] + __half2float(yp[c]);
        v[i] = tt; sum += tt; sq = fmaf(tt, tt, sq);
    }
    #pragma unroll
    for (int o = 16; o; o >>= 1) {
        sum += __shfl_xor_sync(0xffffffffu, sum, o);
        sq  += __shfl_xor_sync(0xffffffffu, sq,  o);
    }
    if (lane == 0) { sh1[grp][w4] = sum; sh2[grp][w4] = sq; }
    __syncthreads();
    if (t == 0) {
        float a = 0.f, c2 = 0.f;
        #pragma unroll
        for (int i = 0; i < 4; ++i) { a += sh1[grp][i]; c2 += sh2[grp][i]; }
        sh1[grp][0] = a; sh2[grp][0] = c2;
    }
    __syncthreads();
    float mu = sh1[grp][0] * (1.f / Dd);
    float rs = rsqrtf(sh2[grp][0] * (1.f / Dd) - mu * mu + 1e-5f);
    __syncthreads();

    sum = 0.f; sq = 0.f;
    #pragma unroll
    for (int i = 0; i < 6; ++i) {
        int c = t + i * 128;
        float tt = (v[i] - mu) * rs * g1[c] + b1[c] + cap[c];
        v[i] = tt; sum += tt; sq = fmaf(tt, tt, sq);
    }
    #pragma unroll
    for (int o = 16; o; o >>= 1) {
        sum += __shfl_xor_sync(0xffffffffu, sum, o);
        sq  += __shfl_xor_sync(0xffffffffu, sq,  o);
    }
    if (lane == 0) { sh1[grp][w4] = sum; sh2[grp][w4] = sq; }
    __syncthreads();
    if (t == 0) {
        float a = 0.f, c2 = 0.f;
        #pragma unroll
        for (int i = 0; i < 4; ++i) { a += sh1[grp][i]; c2 += sh2[grp][i]; }
        sh1[grp][0] = a; sh2[grp][0] = c2;
    }
    __syncthreads();
    float mu2 = sh1[grp][0] * (1.f / Dd);
    float rs2 = rsqrtf(sh2[grp][0] * (1.f / Dd) - mu2 * mu2 + 1e-5f);
    #pragma unroll
    for (int i = 0; i < 6; ++i) {
        int c = t + i * 128;
        float o = (v[i] - mu2) * rs2 * g2[c] + b2[c];
        xp[c] = o;
        x16[(size_t)row * Dd + c] = __float2half(o);
    }
}

// ================= flash-attention: paired q-blocks, single wave ================
// grid = 256 CTAs. CTA (pair, h, b) processes qidx = pair then qidx = 3 - pair
// (tile counts 4+16 / 8+12 — both 20 → perfect balance, 0.86 wave).
#define FATT_SMEM 66560
#define QPITCH 208

__global__ void __launch_bounds__(256) attn_flash(
    const __half* __restrict__ qkv, __half* __restrict__ o16)
{
    extern __shared__ char smd[];
    const int bid  = blockIdx.x;
    const int pair = bid >> 7;           // 0 or 1
    const int rem  = bid & 127;
    const int h    = rem >> 4;
    const int b    = rem & 15;
    const int tid  = threadIdx.x;
    const int lane = tid & 31;
    const int wid  = tid >> 5;
    const uint32_t sQ  = smem_u32(smd);
    const uint32_t sKV = sQ + 26624;
    const float scale2 = rsqrtf((float)DHd) * 1.4426950408889634f;

    auto load_kv = [&](int jt, int s) {
        #pragma unroll
        for (int i = 0; i < 3; ++i) {
            int c = tid + 256 * i;
            int kv = (c >= 384) ? 1 : 0;
            int cc = c - kv * 384;
            int row = cc / 12, dc = cc - row * 12;
            cp_async16(sKV + s * 13312 + kv * 6656 + row * QPITCH + dc * 16,
                       qkv + (size_t)(b * Ss + jt + row) * QKVS + (1 + kv) * Dd
                           + h * DHd + dc * 8, 16);
        }
        CP_COMMIT();
    };

    #pragma unroll 1
    for (int pi = 0; pi < 2; ++pi) {
        const int qidx = pi == 0 ? (3 - pair) : pair;  // long block first
        const int qb   = qidx * 128;
        const int ntiles = qidx * 4 + 4;

        __syncthreads();   // protect sQ/sKV reuse across iterations

        // stage Q
        #pragma unroll
        for (int i = 0; i < 6; ++i) {
            int c = tid + 256 * i;
            int row = c / 12, dc = c - row * 12;
            cp_async16(sQ + row * QPITCH + dc * 16,
                       qkv + (size_t)(b * Ss + qb + row) * QKVS + h * DHd + dc * 8, 16);
        }
        CP_COMMIT();
        load_kv(0, 0);
        load_kv(32, 1);
        CP_WAIT(2);        // Q complete
        __syncthreads();

        uint32_t qf[6][4];
        {
            uint32_t base = sQ + (wid * 16 + (lane & 15)) * QPITCH + ((lane >> 4) << 3) * 2;
            #pragma unroll
            for (int ks = 0; ks < 6; ++ks)
                ldm_x4(qf[ks], base + ks * 32);
        }

        float oacc[12][4];
        #pragma unroll
        for (int i = 0; i < 12; ++i)
            #pragma unroll
            for (int r = 0; r < 4; ++r) oacc[i][r] = 0.f;
        float m0 = -1e30f, m1 = -1e30f, l0 = 0.f, l1 = 0.f;

        const int my_last = qb + wid * 16 + 15;
        const int r0g     = qb + wid * 16 + (lane >> 2);

        for (int t = 0; t < ntiles; ++t) {
            const int jt = t * 32;
            if (t + 1 < ntiles) { CP_WAIT(1); } else { CP_WAIT(0); }
            __syncthreads();
            if (t + 2 < ntiles) load_kv((t + 2) * 32, (t + 2) % 3);

            if (jt <= my_last) {
                const uint32_t kb = sKV + (t % 3) * 13312;
                const uint32_t vb = kb + 6656;

                float sacc[4][4];
                #pragma unroll
                for (int i = 0; i < 4; ++i)
                    #pragma unroll
                    for (int r = 0; r < 4; ++r) sacc[i][r] = 0.f;
                const uint32_t kbase = kb + ((lane & 7) + ((lane >> 4) << 3)) * QPITCH
                                     + (((lane >> 3) & 1) << 4);
                #pragma unroll
                for (int ks = 0; ks < 6; ++ks) {
                    uint32_t kf[4], kg[4];
                    ldm_x4(kf, kbase + ks * 32);
                    ldm_x4(kg, kbase + 16 * QPITCH + ks * 32);
                    mma16816(sacc[0], qf[ks], &kf[0]);
                    mma16816(sacc[1], qf[ks], &kf[2]);
                    mma16816(sacc[2], qf[ks], &kg[0]);
                    mma16816(sacc[3], qf[ks], &kg[2]);
                }

                #pragma unroll
                for (int nb = 0; nb < 4; ++nb)
                    #pragma unroll
                    for (int e = 0; e < 4; ++e) {
                        int j = jt + nb * 8 + (lane & 3) * 2 + (e & 1);
                        int r = r0g + ((e >> 1) << 3);
                        float v = sacc[nb][e] * scale2;
                        sacc[nb][e] = (j <= r) ? v : -1e30f;
                    }

                float mx0 = -1e30f, mx1 = -1e30f;
                #pragma unroll
                for (int nb = 0; nb < 4; ++nb) {
                    mx0 = fmaxf(mx0, fmaxf(sacc[nb][0], sacc[nb][1]));
                    mx1 = fmaxf(mx1, fmaxf(sacc[nb][2], sacc[nb][3]));
                }
                mx0 = fmaxf(mx0, __shfl_xor_sync(0xffffffffu, mx0, 1));
                mx0 = fmaxf(mx0, __shfl_xor_sync(0xffffffffu, mx0, 2));
                mx1 = fmaxf(mx1, __shfl_xor_sync(0xffffffffu, mx1, 1));
                mx1 = fmaxf(mx1, __shfl_xor_sync(0xffffffffu, mx1, 2));
                float mn0 = fmaxf(m0, mx0), mn1 = fmaxf(m1, mx1);

                if (__any_sync(0xffffffffu, (mn0 > m0) || (mn1 > m1))) {
                    float f0 = ex2(m0 - mn0), f1 = ex2(m1 - mn1);
                    l0 *= f0; l1 *= f1;
                    #pragma unroll
                    for (int c6 = 0; c6 < 12; ++c6) {
                        oacc[c6][0] *= f0; oacc[c6][1] *= f0;
                        oacc[c6][2] *= f1; oacc[c6][3] *= f1;
                    }
                }
                m0 = mn0; m1 = mn1;

                float s0 = 0.f, s1 = 0.f;
                #pragma unroll
                for (int nb = 0; nb < 4; ++nb) {
                    float p0 = ex2(sacc[nb][0] - mn0);
                    float p1 = ex2(sacc[nb][1] - mn0);
                    float p2 = ex2(sacc[nb][2] - mn1);
                    float p3 = ex2(sacc[nb][3] - mn1);
                    sacc[nb][0] = p0; sacc[nb][1] = p1;
                    sacc[nb][2] = p2; sacc[nb][3] = p3;
                    s0 += p0 + p1; s1 += p2 + p3;
                }
                s0 += __shfl_xor_sync(0xffffffffu, s0, 1);
                s0 += __shfl_xor_sync(0xffffffffu, s0, 2);
                s1 += __shfl_xor_sync(0xffffffffu, s1, 1);
                s1 += __shfl_xor_sync(0xffffffffu, s1, 2);
                l0 += s0;
                l1 += s1;

                uint32_t pa[2][4];
                #pragma unroll
                for (int kk = 0; kk < 2; ++kk) {
                    pa[kk][0] = pack_h2(sacc[kk*2][0],   sacc[kk*2][1]);
                    pa[kk][1] = pack_h2(sacc[kk*2][2],   sacc[kk*2][3]);
                    pa[kk][2] = pack_h2(sacc[kk*2+1][0], sacc[kk*2+1][1]);
                    pa[kk][3] = pack_h2(sacc[kk*2+1][2], sacc[kk*2+1][3]);
                }

                const uint32_t vrow = vb + ((lane & 7) + (((lane >> 3) & 1) << 3)) * QPITCH;
                #pragma unroll
                for (int kk = 0; kk < 2; ++kk) {
                    #pragma unroll
                    for (int c6 = 0; c6 < 6; ++c6) {
                        uint32_t vf[4];
                        ldm_trans_x4(vf, vrow + kk * 16 * QPITCH
                                         + (c6 * 16 + ((lane >> 4) << 3)) * 2);
                        mma16816(oacc[c6 * 2],     pa[kk], &vf[0]);
                        mma16816(oacc[c6 * 2 + 1], pa[kk], &vf[2]);
                    }
                }
            }
        }

        float il0 = 1.f / l0, il1 = 1.f / l1;
        #pragma unroll
        for (int c6 = 0; c6 < 12; ++c6) {
            int col = h * DHd + c6 * 8 + (lane & 3) * 2;
            *(__half2*)(o16 + (size_t)(b * Ss + r0g) * Dd + col) =
                __floats2half2_rn(oacc[c6][0] * il0, oacc[c6][1] * il0);
            *(__half2*)(o16 + (size_t)(b * Ss + r0g + 8) * Dd + col) =
                __floats2half2_rn(oacc[c6][2] * il1, oacc[c6][3] * il1);
        }
    }
}

// ================= launcher =================
extern "C" void kernel_launch(void* const* d_in, const int* in_sizes, int n_in,
                              void* d_out, int out_size)
{
    (void)in_sizes; (void)n_in; (void)out_size;
    const float* latent   = (const float*)d_in[0];
    const int*   target   = (const int*)  d_in[1];
    const float* tok_emb  = (const float*)d_in[2];
    const float* pos_emb  = (const float*)d_in[3];
    const float* sa_w_qkv = (const float*)d_in[4];
    const float* sa_b_qkv = (const float*)d_in[5];
    const float* sa_w_o   = (const float*)d_in[6];
    const float* sa_b_o   = (const float*)d_in[7];
    const float* ca_w_qkv = (const float*)d_in[8];
    const float* ca_b_qkv = (const float*)d_in[9];
    const float* ca_w_o   = (const float*)d_in[10];
    const float* ca_b_o   = (const float*)d_in[11];
    const float* ffn_w1   = (const float*)d_in[12];
    const float* ffn_b1   = (const float*)d_in[13];
    const float* ffn_w2   = (const float*)d_in[14];
    const float* ffn_b2   = (const float*)d_in[15];
    const float* ln1_g    = (const float*)d_in[16];
    const float* ln1_b    = (const float*)d_in[17];
    const float* ln2_g    = (const float*)d_in[18];
    const float* ln2_b    = (const float*)d_in[19];
    const float* ln3_g    = (const float*)d_in[20];
    const float* ln3_b    = (const float*)d_in[21];
    const float* out_w    = (const float*)d_in[22];
    const float* out_b    = (const float*)d_in[23];

    float *x, *cat, *ca;
    __half *x16, *o16, *y16, *h16, *qkv16, *wqkv16, *wo16, *w116, *w216, *wout16;
    cudaGetSymbolAddress((void**)&x,   g_x);
    cudaGetSymbolAddress((void**)&cat, g_cat);
    cudaGetSymbolAddress((void**)&ca,  g_ca);
    cudaGetSymbolAddress((void**)&x16, g_x16);
    cudaGetSymbolAddress((void**)&o16, g_o16);
    cudaGetSymbolAddress((void**)&y16, g_y16);
    cudaGetSymbolAddress((void**)&h16, g_h16);
    cudaGetSymbolAddress((void**)&qkv16, g_qkv16);
    cudaGetSymbolAddress((void**)&wqkv16, g_wqkv16);
    cudaGetSymbolAddress((void**)&wo16,   g_wo16);
    cudaGetSymbolAddress((void**)&w116,   g_w116);
    cudaGetSymbolAddress((void**)&w216,   g_w216);
    cudaGetSymbolAddress((void**)&wout16, g_wout16);

    cudaFuncSetAttribute(gemm_fp16,  cudaFuncAttributeMaxDynamicSharedMemorySize, GEMM_SMEM);
    cudaFuncSetAttribute(attn_flash, cudaFuncAttributeMaxDynamicSharedMemorySize, FATT_SMEM);

    // 0: weight conversions
    const int nb0 = (Ll*3*Dd*Dd) / 1024, nb1 = (Ll*Dd*Dd) / 1024,
              nb2 = (Ll*Ff*Dd) / 1024,   nb3 = (Ll*Dd*Ff) / 1024,
              nb4 = (Vv*Dd) / 1024;
    convert_all<<<nb0 + nb1 + nb2 + nb3 + nb4, 256>>>(
        sa_w_qkv, wqkv16, nb0, sa_w_o, wo16, nb1,
        ffn_w1, w116, nb2, ffn_w2, w216, nb3, out_w, wout16, nb4);

    // 1: embed
    embed_kernel<<<Mm, 256>>>(target, tok_emb, pos_emb, x, x16);

    // 2: batched cross-attn stage-1
    const int SGB = (Ll * Bb * Dd) / 8;
    small_gemm_all<<<SGB, 256>>>(
        latent, 0,
        ca_w_qkv + (size_t)2*Dd*Dd, (size_t)3*Dd*Dd,
        ca_b_qkv + 2*Dd, 3*Dd, cat);

    // 3: QKV gemm (layer 0), 4: attention (256 CTAs, paired), 5: O-proj
    gemm_fp16<<<dim3(18, 64), 128, GEMM_SMEM>>>(
        x16, wqkv16, sa_b_qkv, nullptr, qkv16, Mm, QKVS, Dd, 2);
    attn_flash<<<256, 256, FATT_SMEM>>>(qkv16, o16);
    gemm_fp16<<<dim3(6, 64), 128, GEMM_SMEM>>>(
        o16, wo16, sa_b_o, nullptr, y16, Mm, Dd, Dd, 2);

    // 6: batched cross-attn stage-2
    small_gemm_all<<<SGB, 256>>>(
        cat, Bb*Dd,
        ca_w_o, (size_t)Dd*Dd,
        ca_b_o, Dd, ca);

    for (int l = 0; l < Ll; ++l) {
        if (l > 0) {
            gemm_fp16<<<dim3(18, 64), 128, GEMM_SMEM>>>(
                x16, wqkv16 + (size_t)l*3*Dd*Dd, sa_b_qkv + (size_t)l*3*Dd,
                nullptr, qkv16, Mm, QKVS, Dd, 2);
            attn_flash<<<256, 256, FATT_SMEM>>>(qkv16, o16);
            gemm_fp16<<<dim3(6, 64), 128, GEMM_SMEM>>>(
                o16, wo16 + (size_t)l*Dd*Dd, sa_b_o + (size_t)l*Dd,
                nullptr, y16, Mm, Dd, Dd, 2);
        }
        add_ln2_kernel<<<Mm/2, 256>>>(x, y16, ca + l*Bb*Dd,
                                      ln1_g + (size_t)l*Dd, ln1_b + (size_t)l*Dd,
                                      ln2_g + (size_t)l*Dd, ln2_b + (size_t)l*Dd, x16);
        gemm_fp16<<<dim3(16, 64), 128, GEMM_SMEM>>>(
            x16, w116 + (size_t)l*Ff*Dd, ffn_b1 + (size_t)l*Ff,
            nullptr, h16, Mm, Ff, Dd, 1);
        gemm_fp16<<<dim3(6, 64), 128, GEMM_SMEM>>>(
            h16, w216 + (size_t)l*Dd*Ff, ffn_b2 + (size_t)l*Dd,
            nullptr, y16, Mm, Dd, Ff, 2);
        add_ln_kernel<<<Mm/2, 256>>>(x, y16, ln3_g + (size_t)l*Dd, ln3_b + (size_t)l*Dd,
                                     x16);
    }

    // output projection (fp32 out)
    gemm_fp16<<<dim3(1, 64), 128, GEMM_SMEM>>>(
        x16, wout16, out_b, (float*)d_out, nullptr, Mm, Vv, Dd, 0);
}

// round 13
// speedup vs baseline: 1.0350x; 1.0350x over previous
#include <cuda_runtime.h>
#include <cuda_fp16.h>
#include <stdint.h>
#include <math.h>

// Problem dims
#define Bb   16
#define Ss   512
#define Dd   768
#define Hh   8
#define Vv   100
#define Ff   2048
#define Ll   6
#define DHd  96
#define Mm   (Bb*Ss)   // 8192
#define QKVS (3*Dd)    // 2304

// ================= low-level helpers =================
__device__ __forceinline__ uint32_t smem_u32(const void* p) {
    return (uint32_t)__cvta_generic_to_shared(p);
}
__device__ __forceinline__ void cp_async16(uint32_t dst, const void* src, int szvalid) {
    asm volatile("cp.async.cg.shared.global [%0], [%1], 16, %2;"
                 :: "r"(dst), "l"(src), "r"(szvalid) : "memory");
}
#define CP_COMMIT() asm volatile("cp.async.commit_group;" ::: "memory")
#define CP_WAIT(n)  asm volatile("cp.async.wait_group %0;" :: "n"(n) : "memory")

__device__ __forceinline__ void ldm_x4(uint32_t* r, uint32_t addr) {
    asm volatile("ldmatrix.sync.aligned.m8n8.x4.shared.b16 {%0,%1,%2,%3}, [%4];"
                 : "=r"(r[0]), "=r"(r[1]), "=r"(r[2]), "=r"(r[3]) : "r"(addr));
}
__device__ __forceinline__ void ldm_trans_x4(uint32_t* r, uint32_t addr) {
    asm volatile("ldmatrix.sync.aligned.m8n8.x4.trans.shared.b16 {%0,%1,%2,%3}, [%4];"
                 : "=r"(r[0]), "=r"(r[1]), "=r"(r[2]), "=r"(r[3]) : "r"(addr));
}
__device__ __forceinline__ void mma16816(float* d, const uint32_t* a, const uint32_t* b) {
    asm volatile("mma.sync.aligned.m16n8k16.row.col.f32.f16.f16.f32 "
                 "{%0,%1,%2,%3}, {%4,%5,%6,%7}, {%8,%9}, {%0,%1,%2,%3};"
                 : "+f"(d[0]), "+f"(d[1]), "+f"(d[2]), "+f"(d[3])
                 : "r"(a[0]), "r"(a[1]), "r"(a[2]), "r"(a[3]), "r"(b[0]), "r"(b[1]));
}
__device__ __forceinline__ uint32_t pack_h2(float a, float b) {
    __half2 t = __floats2half2_rn(a, b);
    return *(uint32_t*)&t;
}
__device__ __forceinline__ float ex2(float x) {
    float y;
    asm("ex2.approx.f32 %0, %1;" : "=f"(y) : "f"(x));
    return y;
}

// ================= device scratch =================
__device__ float g_x   [Mm * Dd];
__device__ float g_cat [Ll * Bb * Dd];
__device__ float g_ca  [Ll * Bb * Dd];

__device__ __align__(16) __half g_x16 [Mm * Dd];
__device__ __align__(16) __half g_o16 [Mm * Dd];
__device__ __align__(16) __half g_y16 [Mm * Dd];
__device__ __align__(16) __half g_h16 [Mm * Ff];
__device__ __align__(16) __half g_qkv16[Mm * QKVS];

__device__ __align__(16) __half g_wqkv16[Ll*3*Dd*Dd];
__device__ __align__(16) __half g_wo16  [Ll*Dd*Dd];
__device__ __align__(16) __half g_w116  [Ll*Ff*Dd];
__device__ __align__(16) __half g_w216  [Ll*Dd*Ff];
__device__ __align__(16) __half g_wout16[Vv*Dd];

// ================= weight convert =================
__global__ __launch_bounds__(256) void convert_all(
    const float* __restrict__ s0, __half* __restrict__ d0, int b0,
    const float* __restrict__ s1, __half* __restrict__ d1, int b1,
    const float* __restrict__ s2, __half* __restrict__ d2, int b2,
    const float* __restrict__ s3, __half* __restrict__ d3, int b3,
    const float* __restrict__ s4, __half* __restrict__ d4, int b4)
{
    int bid = blockIdx.x;
    const float* src; __half* dst; int nb;
    if      (bid < b0)          { src = s0; dst = d0; nb = bid; }
    else if (bid < b0+b1)       { src = s1; dst = d1; nb = bid - b0; }
    else if (bid < b0+b1+b2)    { src = s2; dst = d2; nb = bid - b0 - b1; }
    else if (bid < b0+b1+b2+b3) { src = s3; dst = d3; nb = bid - b0 - b1 - b2; }
    else                        { src = s4; dst = d4; nb = bid - b0 - b1 - b2 - b3; }
    int i = (nb * 256 + threadIdx.x) * 4;
    float4 v = *(const float4*)&src[i];
    *(__half2*)&dst[i]     = __floats2half2_rn(v.x, v.y);
    *(__half2*)&dst[i + 2] = __floats2half2_rn(v.z, v.w);
}

// ================= embed =================
__global__ __launch_bounds__(256) void embed_kernel(
    const int* __restrict__ target, const float* __restrict__ tok,
    const float* __restrict__ pos, float* __restrict__ x,
    __half* __restrict__ x16)
{
    int row = blockIdx.x;
    int s   = row & (Ss - 1);
    int t   = target[row];
    const float* tp = tok + (size_t)t * Dd;
    const float* pp = pos + (size_t)s * Dd;
    size_t base = (size_t)row * Dd;
    for (int c = threadIdx.x; c < Dd; c += 256) {
        float v = tp[c] + pp[c];
        x[base + c] = v;
        x16[base + c] = __float2half(v);
    }
}

// ================= fp16 GEMM: CTA 128x128, 4 warps, 3-stage (FROZEN) =========
#define BKc 32
#define APITCH 80
#define T128_B   (128*APITCH)
#define STAGE_B  (2*T128_B)
#define GEMM_SMEM (3*STAGE_B)

__global__ void __launch_bounds__(128, 3) gemm_fp16(
    const __half* __restrict__ A, const __half* __restrict__ W,
    const float* __restrict__ bias, float* __restrict__ C,
    __half* __restrict__ Ch,
    int M, int N, int K, int mode)
{
    extern __shared__ char sm[];
    const uint32_t smU = smem_u32(sm);
    const int tid  = threadIdx.x;
    const int lane = tid & 31;
    const int wid  = tid >> 5;
    const int bm   = blockIdx.y * 128;
    const int bn   = blockIdx.x * 128;
    const int wm   = (wid >> 1) * 64;
    const int wn   = (wid & 1) * 64;

    float acc[4][8][4];
    #pragma unroll
    for (int i = 0; i < 4; ++i)
        #pragma unroll
        for (int j = 0; j < 8; ++j)
            #pragma unroll
            for (int r = 0; r < 4; ++r) acc[i][j][r] = 0.f;

    const int NC = K / BKc;

    auto issue = [&](int chunk, int s) {
        const int k0 = chunk * BKc;
        #pragma unroll
        for (int i = 0; i < 4; ++i) {
            int c = tid + 128 * i;
            int row = c >> 2, c16 = c & 3;
            cp_async16(smU + s * STAGE_B + row * APITCH + c16 * 16,
                       (const char*)(A + (size_t)(bm + row) * K + k0) + c16 * 16, 16);
        }
        #pragma unroll
        for (int i = 0; i < 4; ++i) {
            int c = tid + 128 * i;
            int row = c >> 2, c16 = c & 3;
            int rn = bn + row;
            const char* g = (const char*)(W + (size_t)rn * K + k0) + c16 * 16;
            int sz = 16;
            if (rn >= N) { sz = 0; g = (const char*)W; }
            cp_async16(smU + s * STAGE_B + T128_B + row * APITCH + c16 * 16, g, sz);
        }
        CP_COMMIT();
    };

    const int wrow_off = ((lane >> 4) << 3) + (lane & 7);
    const int wcol_off = ((lane >> 3) & 1) * 8;
    const int arow_off = lane & 15;
    const int acol_off = (lane >> 4) << 3;

    auto compute = [&](int s) {
        const uint32_t aB = smU + s * STAGE_B;
        const uint32_t wB = aB + T128_B;
        #pragma unroll
        for (int ks = 0; ks < BKc; ks += 16) {
            uint32_t wh[4][4];
            #pragma unroll
            for (int nb = 0; nb < 4; ++nb)
                ldm_x4(wh[nb], wB + (wn + nb * 16 + wrow_off) * APITCH + (ks + wcol_off) * 2);
            #pragma unroll
            for (int mi = 0; mi < 4; ++mi) {
                uint32_t ah[4];
                ldm_x4(ah, aB + (wm + mi * 16 + arow_off) * APITCH + (ks + acol_off) * 2);
                #pragma unroll
                for (int nb = 0; nb < 4; ++nb) {
                    mma16816(&acc[mi][nb * 2][0],     ah, &wh[nb][0]);
                    mma16816(&acc[mi][nb * 2 + 1][0], ah, &wh[nb][2]);
                }
            }
        }
    };

    issue(0, 0);
    issue(1, 1);
    for (int c = 0; c < NC; ++c) {
        if (c + 1 < NC) { CP_WAIT(1); } else { CP_WAIT(0); }
        __syncthreads();
        if (c + 2 < NC) issue(c + 2, (c + 2) % 3);
        compute(c % 3);
    }

    float bs[16];
    #pragma unroll
    for (int nj = 0; nj < 8; ++nj) {
        int c0 = bn + wn + nj * 8 + (lane & 3) * 2;
        bs[nj * 2]     = (c0 < N)     ? bias[c0]     : 0.f;
        bs[nj * 2 + 1] = (c0 + 1 < N) ? bias[c0 + 1] : 0.f;
    }
    #pragma unroll
    for (int mi = 0; mi < 4; ++mi) {
        #pragma unroll
        for (int nj = 0; nj < 8; ++nj) {
            int c0 = bn + wn + nj * 8 + (lane & 3) * 2;
            if (c0 >= N) continue;
            #pragma unroll
            for (int p = 0; p < 2; ++p) {
                int row = bm + wm + mi * 16 + (lane >> 2) + p * 8;
                float v0 = acc[mi][nj][p * 2]     + bs[nj * 2];
                float v1 = acc[mi][nj][p * 2 + 1] + bs[nj * 2 + 1];
                if (mode == 0) {
                    *(float2*)(C + (size_t)row * N + c0) = make_float2(v0, v1);
                } else {
                    if (mode == 1) { v0 = fmaxf(v0, 0.f); v1 = fmaxf(v1, 0.f); }
                    *(__half2*)(Ch + (size_t)row * N + c0) = __floats2half2_rn(v0, v1);
                }
            }
        }
    }
}

// ================= batched tiny GEMM (all layers in one launch) =================
__global__ __launch_bounds__(256) void small_gemm_all(
    const float* __restrict__ A, int aStrideL,
    const float* __restrict__ W, size_t wStrideL,
    const float* __restrict__ bias, int biasStrideL,
    float* __restrict__ C)
{
    int wg   = blockIdx.x * 8 + (threadIdx.x >> 5);
    int lane = threadIdx.x & 31;
    if (wg >= Ll * Bb * Dd) return;
    int l  = wg / (Bb * Dd);
    int r  = wg - l * (Bb * Dd);
    int bq = r / Dd;
    int n  = r - bq * Dd;
    const float* a = A + (size_t)l * aStrideL + (size_t)bq * Dd;
    const float* w = W + (size_t)l * wStrideL + (size_t)n * Dd;
    float s = 0.f;
    #pragma unroll 4
    for (int k = lane; k < Dd; k += 32) s = fmaf(a[k], w[k], s);
    #pragma unroll
    for (int o = 16; o; o >>= 1) s += __shfl_xor_sync(0xffffffffu, s, o);
    if (lane == 0) C[wg] = s + bias[(size_t)l * biasStrideL + n];
}

// ================= add+LN (ln3): 4 rows per 256-thread block =================
__global__ __launch_bounds__(256) void add_ln_kernel(
    float* __restrict__ x, const __half* __restrict__ y16,
    const float* __restrict__ g, const float* __restrict__ b,
    __half* __restrict__ x16)
{
    const int tid = threadIdx.x;
    const int grp = tid >> 6;            // 0..3: which row
    const int t   = tid & 63;
    const int row = blockIdx.x * 4 + grp;
    const __half* yp = y16 + (size_t)row * Dd;
    float* xp = x + (size_t)row * Dd;
    __shared__ float sh1[4][2], sh2[4][2];
    const int w2   = (tid >> 5) & 1;     // warp within group
    const int lane = tid & 31;

    float v[12];
    float sum = 0.f, sq = 0.f;
    #pragma unroll
    for (int i = 0; i < 12; ++i) {
        int c = t + i * 64;
        float tt = xp[c] + __half2float(yp[c]);
        v[i] = tt; sum += tt; sq = fmaf(tt, tt, sq);
    }
    #pragma unroll
    for (int o = 16; o; o >>= 1) {
        sum += __shfl_xor_sync(0xffffffffu, sum, o);
        sq  += __shfl_xor_sync(0xffffffffu, sq,  o);
    }
    if (lane == 0) { sh1[grp][w2] = sum; sh2[grp][w2] = sq; }
    __syncthreads();
    float mu  = (sh1[grp][0] + sh1[grp][1]) * (1.f / Dd);
    float var = (sh2[grp][0] + sh2[grp][1]) * (1.f / Dd) - mu * mu;
    float rs  = rsqrtf(var + 1e-5f);
    #pragma unroll
    for (int i = 0; i < 12; ++i) {
        int c = t + i * 64;
        float o = (v[i] - mu) * rs * g[c] + b[c];
        xp[c] = o;
        x16[(size_t)row * Dd + c] = __float2half(o);
    }
}

// ================= fused (add+LN1)+(add bcast+LN2): 4 rows per block ===========
__global__ __launch_bounds__(256) void add_ln2_kernel(
    float* __restrict__ x, const __half* __restrict__ y16,
    const float* __restrict__ ca,
    const float* __restrict__ g1, const float* __restrict__ b1,
    const float* __restrict__ g2, const float* __restrict__ b2,
    __half* __restrict__ x16)
{
    const int tid = threadIdx.x;
    const int grp = tid >> 6;
    const int t   = tid & 63;
    const int row = blockIdx.x * 4 + grp;
    const __half* yp  = y16 + (size_t)row * Dd;
    const float* cap  = ca  + (size_t)(row >> 9) * Dd;
    float* xp = x + (size_t)row * Dd;
    __shared__ float sh1[4][2], sh2[4][2];
    const int w2   = (tid >> 5) & 1;
    const int lane = tid & 31;

    float v[12];
    float sum = 0.f, sq = 0.f;
    #pragma unroll
    for (int i = 0; i < 12; ++i) {
        int c = t + i * 64;
        float tt = xp[c] + __half2float(yp[c]);
        v[i] = tt; sum += tt; sq = fmaf(tt, tt, sq);
    }
    #pragma unroll
    for (int o = 16; o; o >>= 1) {
        sum += __shfl_xor_sync(0xffffffffu, sum, o);
        sq  += __shfl_xor_sync(0xffffffffu, sq,  o);
    }
    if (lane == 0) { sh1[grp][w2] = sum; sh2[grp][w2] = sq; }
    __syncthreads();
    float mu = (sh1[grp][0] + sh1[grp][1]) * (1.f / Dd);
    float rs = rsqrtf((sh2[grp][0] + sh2[grp][1]) * (1.f / Dd) - mu * mu + 1e-5f);
    __syncthreads();

    // second add + LN
    sum = 0.f; sq = 0.f;
    #pragma unroll
    for (int i = 0; i < 12; ++i) {
        int c = t + i * 64;
        float tt = (v[i] - mu) * rs * g1[c] + b1[c] + cap[c];
        v[i] = tt; sum += tt; sq = fmaf(tt, tt, sq);
    }
    #pragma unroll
    for (int o = 16; o; o >>= 1) {
        sum += __shfl_xor_sync(0xffffffffu, sum, o);
        sq  += __shfl_xor_sync(0xffffffffu, sq,  o);
    }
    if (lane == 0) { sh1[grp][w2] = sum; sh2[grp][w2] = sq; }
    __syncthreads();
    float mu2 = (sh1[grp][0] + sh1[grp][1]) * (1.f / Dd);
    float rs2 = rsqrtf((sh2[grp][0] + sh2[grp][1]) * (1.f / Dd) - mu2 * mu2 + 1e-5f);
    #pragma unroll
    for (int i = 0; i < 12; ++i) {
        int c = t + i * 64;
        float o = (v[i] - mu2) * rs2 * g2[c] + b2[c];
        xp[c] = o;
        x16[(size_t)row * Dd + c] = __float2half(o);
    }
}

// ================= flash-attention: 3-stage KV, long-first (r10 form) ===========
#define FATT_SMEM 66560
#define QPITCH 208

__global__ void __launch_bounds__(256) attn_flash(
    const __half* __restrict__ qkv, __half* __restrict__ o16)
{
    extern __shared__ char smd[];
    const int bid  = blockIdx.x;
    const int qidx = (Ss/128 - 1) - (bid >> 7);   // longest blocks first
    const int rem  = bid & 127;
    const int h    = rem >> 4;
    const int b    = rem & 15;
    const int qb   = qidx * 128;
    const int tid  = threadIdx.x;
    const int lane = tid & 31;
    const int wid  = tid >> 5;
    const uint32_t sQ  = smem_u32(smd);
    const uint32_t sKV = sQ + 26624;
    const float scale2 = rsqrtf((float)DHd) * 1.4426950408889634f;

    #pragma unroll
    for (int i = 0; i < 6; ++i) {
        int c = tid + 256 * i;
        int row = c / 12, dc = c - row * 12;
        cp_async16(sQ + row * QPITCH + dc * 16,
                   qkv + (size_t)(b * Ss + qb + row) * QKVS + h * DHd + dc * 8, 16);
    }
    CP_COMMIT();

    auto load_kv = [&](int jt, int s) {
        #pragma unroll
        for (int i = 0; i < 3; ++i) {
            int c = tid + 256 * i;
            int kv = (c >= 384) ? 1 : 0;
            int cc = c - kv * 384;
            int row = cc / 12, dc = cc - row * 12;
            cp_async16(sKV + s * 13312 + kv * 6656 + row * QPITCH + dc * 16,
                       qkv + (size_t)(b * Ss + jt + row) * QKVS + (1 + kv) * Dd
                           + h * DHd + dc * 8, 16);
        }
        CP_COMMIT();
    };

    const int ntiles  = (qb + 128) / 32;
    load_kv(0, 0);
    load_kv(32, 1);
    CP_WAIT(2);
    __syncthreads();

    uint32_t qf[6][4];
    {
        uint32_t base = sQ + (wid * 16 + (lane & 15)) * QPITCH + ((lane >> 4) << 3) * 2;
        #pragma unroll
        for (int ks = 0; ks < 6; ++ks)
            ldm_x4(qf[ks], base + ks * 32);
    }

    float oacc[12][4];
    #pragma unroll
    for (int i = 0; i < 12; ++i)
        #pragma unroll
        for (int r = 0; r < 4; ++r) oacc[i][r] = 0.f;
    float m0 = -1e30f, m1 = -1e30f, l0 = 0.f, l1 = 0.f;

    const int my_last = qb + wid * 16 + 15;
    const int r0g     = qb + wid * 16 + (lane >> 2);

    for (int t = 0; t < ntiles; ++t) {
        const int jt = t * 32;
        if (t + 1 < ntiles) { CP_WAIT(1); } else { CP_WAIT(0); }
        __syncthreads();
        if (t + 2 < ntiles) load_kv((t + 2) * 32, (t + 2) % 3);

        if (jt <= my_last) {
            const uint32_t kb = sKV + (t % 3) * 13312;
            const uint32_t vb = kb + 6656;

            float sacc[4][4];
            #pragma unroll
            for (int i = 0; i < 4; ++i)
                #pragma unroll
                for (int r = 0; r < 4; ++r) sacc[i][r] = 0.f;
            const uint32_t kbase = kb + ((lane & 7) + ((lane >> 4) << 3)) * QPITCH
                                 + (((lane >> 3) & 1) << 4);
            #pragma unroll
            for (int ks = 0; ks < 6; ++ks) {
                uint32_t kf[4], kg[4];
                ldm_x4(kf, kbase + ks * 32);
                ldm_x4(kg, kbase + 16 * QPITCH + ks * 32);
                mma16816(sacc[0], qf[ks], &kf[0]);
                mma16816(sacc[1], qf[ks], &kf[2]);
                mma16816(sacc[2], qf[ks], &kg[0]);
                mma16816(sacc[3], qf[ks], &kg[2]);
            }

            #pragma unroll
            for (int nb = 0; nb < 4; ++nb)
                #pragma unroll
                for (int e = 0; e < 4; ++e) {
                    int j = jt + nb * 8 + (lane & 3) * 2 + (e & 1);
                    int r = r0g + ((e >> 1) << 3);
                    float v = sacc[nb][e] * scale2;
                    sacc[nb][e] = (j <= r) ? v : -1e30f;
                }

            float mx0 = -1e30f, mx1 = -1e30f;
            #pragma unroll
            for (int nb = 0; nb < 4; ++nb) {
                mx0 = fmaxf(mx0, fmaxf(sacc[nb][0], sacc[nb][1]));
                mx1 = fmaxf(mx1, fmaxf(sacc[nb][2], sacc[nb][3]));
            }
            mx0 = fmaxf(mx0, __shfl_xor_sync(0xffffffffu, mx0, 1));
            mx0 = fmaxf(mx0, __shfl_xor_sync(0xffffffffu, mx0, 2));
            mx1 = fmaxf(mx1, __shfl_xor_sync(0xffffffffu, mx1, 1));
            mx1 = fmaxf(mx1, __shfl_xor_sync(0xffffffffu, mx1, 2));
            float mn0 = fmaxf(m0, mx0), mn1 = fmaxf(m1, mx1);

            if (__any_sync(0xffffffffu, (mn0 > m0) || (mn1 > m1))) {
                float f0 = ex2(m0 - mn0), f1 = ex2(m1 - mn1);
                l0 *= f0; l1 *= f1;
                #pragma unroll
                for (int c6 = 0; c6 < 12; ++c6) {
                    oacc[c6][0] *= f0; oacc[c6][1] *= f0;
                    oacc[c6][2] *= f1; oacc[c6][3] *= f1;
                }
            }
            m0 = mn0; m1 = mn1;

            float s0 = 0.f, s1 = 0.f;
            #pragma unroll
            for (int nb = 0; nb < 4; ++nb) {
                float p0 = ex2(sacc[nb][0] - mn0);
                float p1 = ex2(sacc[nb][1] - mn0);
                float p2 = ex2(sacc[nb][2] - mn1);
                float p3 = ex2(sacc[nb][3] - mn1);
                sacc[nb][0] = p0; sacc[nb][1] = p1;
                sacc[nb][2] = p2; sacc[nb][3] = p3;
                s0 += p0 + p1; s1 += p2 + p3;
            }
            s0 += __shfl_xor_sync(0xffffffffu, s0, 1);
            s0 += __shfl_xor_sync(0xffffffffu, s0, 2);
            s1 += __shfl_xor_sync(0xffffffffu, s1, 1);
            s1 += __shfl_xor_sync(0xffffffffu, s1, 2);
            l0 += s0;
            l1 += s1;

            uint32_t pa[2][4];
            #pragma unroll
            for (int kk = 0; kk < 2; ++kk) {
                pa[kk][0] = pack_h2(sacc[kk*2][0],   sacc[kk*2][1]);
                pa[kk][1] = pack_h2(sacc[kk*2][2],   sacc[kk*2][3]);
                pa[kk][2] = pack_h2(sacc[kk*2+1][0], sacc[kk*2+1][1]);
                pa[kk][3] = pack_h2(sacc[kk*2+1][2], sacc[kk*2+1][3]);
            }

            const uint32_t vrow = vb + ((lane & 7) + (((lane >> 3) & 1) << 3)) * QPITCH;
            #pragma unroll
            for (int kk = 0; kk < 2; ++kk) {
                #pragma unroll
                for (int c6 = 0; c6 < 6; ++c6) {
                    uint32_t vf[4];
                    ldm_trans_x4(vf, vrow + kk * 16 * QPITCH
                                     + (c6 * 16 + ((lane >> 4) << 3)) * 2);
                    mma16816(oacc[c6 * 2],     pa[kk], &vf[0]);
                    mma16816(oacc[c6 * 2 + 1], pa[kk], &vf[2]);
                }
            }
        }
    }

    float il0 = 1.f / l0, il1 = 1.f / l1;
    #pragma unroll
    for (int c6 = 0; c6 < 12; ++c6) {
        int col = h * DHd + c6 * 8 + (lane & 3) * 2;
        *(__half2*)(o16 + (size_t)(b * Ss + r0g) * Dd + col) =
            __floats2half2_rn(oacc[c6][0] * il0, oacc[c6][1] * il0);
        *(__half2*)(o16 + (size_t)(b * Ss + r0g + 8) * Dd + col) =
            __floats2half2_rn(oacc[c6][2] * il1, oacc[c6][3] * il1);
    }
}

// ================= launcher =================
extern "C" void kernel_launch(void* const* d_in, const int* in_sizes, int n_in,
                              void* d_out, int out_size)
{
    (void)in_sizes; (void)n_in; (void)out_size;
    const float* latent   = (const float*)d_in[0];
    const int*   target   = (const int*)  d_in[1];
    const float* tok_emb  = (const float*)d_in[2];
    const float* pos_emb  = (const float*)d_in[3];
    const float* sa_w_qkv = (const float*)d_in[4];
    const float* sa_b_qkv = (const float*)d_in[5];
    const float* sa_w_o   = (const float*)d_in[6];
    const float* sa_b_o   = (const float*)d_in[7];
    const float* ca_w_qkv = (const float*)d_in[8];
    const float* ca_b_qkv = (const float*)d_in[9];
    const float* ca_w_o   = (const float*)d_in[10];
    const float* ca_b_o   = (const float*)d_in[11];
    const float* ffn_w1   = (const float*)d_in[12];
    const float* ffn_b1   = (const float*)d_in[13];
    const float* ffn_w2   = (const float*)d_in[14];
    const float* ffn_b2   = (const float*)d_in[15];
    const float* ln1_g    = (const float*)d_in[16];
    const float* ln1_b    = (const float*)d_in[17];
    const float* ln2_g    = (const float*)d_in[18];
    const float* ln2_b    = (const float*)d_in[19];
    const float* ln3_g    = (const float*)d_in[20];
    const float* ln3_b    = (const float*)d_in[21];
    const float* out_w    = (const float*)d_in[22];
    const float* out_b    = (const float*)d_in[23];

    float *x, *cat, *ca;
    __half *x16, *o16, *y16, *h16, *qkv16, *wqkv16, *wo16, *w116, *w216, *wout16;
    cudaGetSymbolAddress((void**)&x,   g_x);
    cudaGetSymbolAddress((void**)&cat, g_cat);
    cudaGetSymbolAddress((void**)&ca,  g_ca);
    cudaGetSymbolAddress((void**)&x16, g_x16);
    cudaGetSymbolAddress((void**)&o16, g_o16);
    cudaGetSymbolAddress((void**)&y16, g_y16);
    cudaGetSymbolAddress((void**)&h16, g_h16);
    cudaGetSymbolAddress((void**)&qkv16, g_qkv16);
    cudaGetSymbolAddress((void**)&wqkv16, g_wqkv16);
    cudaGetSymbolAddress((void**)&wo16,   g_wo16);
    cudaGetSymbolAddress((void**)&w116,   g_w116);
    cudaGetSymbolAddress((void**)&w216,   g_w216);
    cudaGetSymbolAddress((void**)&wout16, g_wout16);

    cudaFuncSetAttribute(gemm_fp16,  cudaFuncAttributeMaxDynamicSharedMemorySize, GEMM_SMEM);
    cudaFuncSetAttribute(attn_flash, cudaFuncAttributeMaxDynamicSharedMemorySize, FATT_SMEM);

    // 0: weight conversions
    const int nb0 = (Ll*3*Dd*Dd) / 1024, nb1 = (Ll*Dd*Dd) / 1024,
              nb2 = (Ll*Ff*Dd) / 1024,   nb3 = (Ll*Dd*Ff) / 1024,
              nb4 = (Vv*Dd) / 1024;
    convert_all<<<nb0 + nb1 + nb2 + nb3 + nb4, 256>>>(
        sa_w_qkv, wqkv16, nb0, sa_w_o, wo16, nb1,
        ffn_w1, w116, nb2, ffn_w2, w216, nb3, out_w, wout16, nb4);

    // 1: embed
    embed_kernel<<<Mm, 256>>>(target, tok_emb, pos_emb, x, x16);

    // 2: batched cross-attn stage-1
    const int SGB = (Ll * Bb * Dd) / 8;
    small_gemm_all<<<SGB, 256>>>(
        latent, 0,
        ca_w_qkv + (size_t)2*Dd*Dd, (size_t)3*Dd*Dd,
        ca_b_qkv + 2*Dd, 3*Dd, cat);

    // 3: QKV gemm (layer 0), 4: attention (512 CTAs, long-first), 5: O-proj
    gemm_fp16<<<dim3(18, 64), 128, GEMM_SMEM>>>(
        x16, wqkv16, sa_b_qkv, nullptr, qkv16, Mm, QKVS, Dd, 2);
    attn_flash<<<512, 256, FATT_SMEM>>>(qkv16, o16);
    gemm_fp16<<<dim3(6, 64), 128, GEMM_SMEM>>>(
        o16, wo16, sa_b_o, nullptr, y16, Mm, Dd, Dd, 2);

    // 6: batched cross-attn stage-2
    small_gemm_all<<<SGB, 256>>>(
        cat, Bb*Dd,
        ca_w_o, (size_t)Dd*Dd,
        ca_b_o, Dd, ca);

    for (int l = 0; l < Ll; ++l) {
        if (l > 0) {
            gemm_fp16<<<dim3(18, 64), 128, GEMM_SMEM>>>(
                x16, wqkv16 + (size_t)l*3*Dd*Dd, sa_b_qkv + (size_t)l*3*Dd,
                nullptr, qkv16, Mm, QKVS, Dd, 2);
            attn_flash<<<512, 256, FATT_SMEM>>>(qkv16, o16);
            gemm_fp16<<<dim3(6, 64), 128, GEMM_SMEM>>>(
                o16, wo16 + (size_t)l*Dd*Dd, sa_b_o + (size_t)l*Dd,
                nullptr, y16, Mm, Dd, Dd, 2);
        }
        add_ln2_kernel<<<Mm/4, 256>>>(x, y16, ca + l*Bb*Dd,
                                      ln1_g + (size_t)l*Dd, ln1_b + (size_t)l*Dd,
                                      ln2_g + (size_t)l*Dd, ln2_b + (size_t)l*Dd, x16);
        gemm_fp16<<<dim3(16, 64), 128, GEMM_SMEM>>>(
            x16, w116 + (size_t)l*Ff*Dd, ffn_b1 + (size_t)l*Ff,
            nullptr, h16, Mm, Ff, Dd, 1);
        gemm_fp16<<<dim3(6, 64), 128, GEMM_SMEM>>>(
            h16, w216 + (size_t)l*Dd*Ff, ffn_b2 + (size_t)l*Dd,
            nullptr, y16, Mm, Dd, Ff, 2);
        add_ln_kernel<<<Mm/4, 256>>>(x, y16, ln3_g + (size_t)l*Dd, ln3_b + (size_t)l*Dd,
                                     x16);
    }

    // output projection (fp32 out)
    gemm_fp16<<<dim3(1, 64), 128, GEMM_SMEM>>>(
        x16, wout16, out_b, (float*)d_out, nullptr, Mm, Vv, Dd, 0);
}

// round 14
// speedup vs baseline: 1.0458x; 1.0104x over previous
#include <cuda_runtime.h>
#include <cuda_fp16.h>
#include <stdint.h>
#include <math.h>

// Problem dims
#define Bb   16
#define Ss   512
#define Dd   768
#define Hh   8
#define Vv   100
#define Ff   2048
#define Ll   6
#define DHd  96
#define Mm   (Bb*Ss)   // 8192
#define QKVS (3*Dd)    // 2304

// ================= low-level helpers =================
__device__ __forceinline__ uint32_t smem_u32(const void* p) {
    return (uint32_t)__cvta_generic_to_shared(p);
}
__device__ __forceinline__ void cp_async16(uint32_t dst, const void* src, int szvalid) {
    asm volatile("cp.async.cg.shared.global [%0], [%1], 16, %2;"
                 :: "r"(dst), "l"(src), "r"(szvalid) : "memory");
}
#define CP_COMMIT() asm volatile("cp.async.commit_group;" ::: "memory")
#define CP_WAIT(n)  asm volatile("cp.async.wait_group %0;" :: "n"(n) : "memory")

__device__ __forceinline__ void ldm_x4(uint32_t* r, uint32_t addr) {
    asm volatile("ldmatrix.sync.aligned.m8n8.x4.shared.b16 {%0,%1,%2,%3}, [%4];"
                 : "=r"(r[0]), "=r"(r[1]), "=r"(r[2]), "=r"(r[3]) : "r"(addr));
}
__device__ __forceinline__ void ldm_trans_x4(uint32_t* r, uint32_t addr) {
    asm volatile("ldmatrix.sync.aligned.m8n8.x4.trans.shared.b16 {%0,%1,%2,%3}, [%4];"
                 : "=r"(r[0]), "=r"(r[1]), "=r"(r[2]), "=r"(r[3]) : "r"(addr));
}
__device__ __forceinline__ void mma16816(float* d, const uint32_t* a, const uint32_t* b) {
    asm volatile("mma.sync.aligned.m16n8k16.row.col.f32.f16.f16.f32 "
                 "{%0,%1,%2,%3}, {%4,%5,%6,%7}, {%8,%9}, {%0,%1,%2,%3};"
                 : "+f"(d[0]), "+f"(d[1]), "+f"(d[2]), "+f"(d[3])
                 : "r"(a[0]), "r"(a[1]), "r"(a[2]), "r"(a[3]), "r"(b[0]), "r"(b[1]));
}
__device__ __forceinline__ uint32_t pack_h2(float a, float b) {
    __half2 t = __floats2half2_rn(a, b);
    return *(uint32_t*)&t;
}
__device__ __forceinline__ float ex2(float x) {
    float y;
    asm("ex2.approx.f32 %0, %1;" : "=f"(y) : "f"(x));
    return y;
}

// ================= device scratch =================
__device__ float g_x   [Mm * Dd];
__device__ float g_cat [Ll * Bb * Dd];
__device__ float g_ca  [Ll * Bb * Dd];

__device__ __align__(16) __half g_x16 [Mm * Dd];
__device__ __align__(16) __half g_o16 [Mm * Dd];
__device__ __align__(16) __half g_y16 [Mm * Dd];
__device__ __align__(16) __half g_h16 [Mm * Ff];
__device__ __align__(16) __half g_qkv16[Mm * QKVS];

__device__ __align__(16) __half g_wqkv16[Ll*3*Dd*Dd];
__device__ __align__(16) __half g_wo16  [Ll*Dd*Dd];
__device__ __align__(16) __half g_w116  [Ll*Ff*Dd];
__device__ __align__(16) __half g_w216  [Ll*Dd*Ff];
__device__ __align__(16) __half g_wout16[Vv*Dd];

// ================= weight convert =================
__global__ __launch_bounds__(256) void convert_all(
    const float* __restrict__ s0, __half* __restrict__ d0, int b0,
    const float* __restrict__ s1, __half* __restrict__ d1, int b1,
    const float* __restrict__ s2, __half* __restrict__ d2, int b2,
    const float* __restrict__ s3, __half* __restrict__ d3, int b3,
    const float* __restrict__ s4, __half* __restrict__ d4, int b4)
{
    int bid = blockIdx.x;
    const float* src; __half* dst; int nb;
    if      (bid < b0)          { src = s0; dst = d0; nb = bid; }
    else if (bid < b0+b1)       { src = s1; dst = d1; nb = bid - b0; }
    else if (bid < b0+b1+b2)    { src = s2; dst = d2; nb = bid - b0 - b1; }
    else if (bid < b0+b1+b2+b3) { src = s3; dst = d3; nb = bid - b0 - b1 - b2; }
    else                        { src = s4; dst = d4; nb = bid - b0 - b1 - b2 - b3; }
    int i = (nb * 256 + threadIdx.x) * 4;
    float4 v = *(const float4*)&src[i];
    *(__half2*)&dst[i]     = __floats2half2_rn(v.x, v.y);
    *(__half2*)&dst[i + 2] = __floats2half2_rn(v.z, v.w);
}

// ================= embed (vectorized: 192 threads x float4) =================
__global__ __launch_bounds__(192) void embed_kernel(
    const int* __restrict__ target, const float* __restrict__ tok,
    const float* __restrict__ pos, float* __restrict__ x,
    __half* __restrict__ x16)
{
    int row = blockIdx.x;
    int s   = row & (Ss - 1);
    int t   = target[row];
    const float* tp = tok + (size_t)t * Dd;
    const float* pp = pos + (size_t)s * Dd;
    size_t base = (size_t)row * Dd;
    int c = threadIdx.x * 4;            // 192*4 = 768
    float4 a = *(const float4*)&tp[c];
    float4 p = *(const float4*)&pp[c];
    float4 v = make_float4(a.x + p.x, a.y + p.y, a.z + p.z, a.w + p.w);
    *(float4*)&x[base + c] = v;
    *(__half2*)&x16[base + c]     = __floats2half2_rn(v.x, v.y);
    *(__half2*)&x16[base + c + 2] = __floats2half2_rn(v.z, v.w);
}

// ================= fp16 GEMM: CTA 128x128, 4 warps, 3-stage (FROZEN) =========
#define BKc 32
#define APITCH 80
#define T128_B   (128*APITCH)
#define STAGE_B  (2*T128_B)
#define GEMM_SMEM (3*STAGE_B)

__global__ void __launch_bounds__(128, 3) gemm_fp16(
    const __half* __restrict__ A, const __half* __restrict__ W,
    const float* __restrict__ bias, float* __restrict__ C,
    __half* __restrict__ Ch,
    int M, int N, int K, int mode)
{
    extern __shared__ char sm[];
    const uint32_t smU = smem_u32(sm);
    const int tid  = threadIdx.x;
    const int lane = tid & 31;
    const int wid  = tid >> 5;
    const int bm   = blockIdx.y * 128;
    const int bn   = blockIdx.x * 128;
    const int wm   = (wid >> 1) * 64;
    const int wn   = (wid & 1) * 64;

    float acc[4][8][4];
    #pragma unroll
    for (int i = 0; i < 4; ++i)
        #pragma unroll
        for (int j = 0; j < 8; ++j)
            #pragma unroll
            for (int r = 0; r < 4; ++r) acc[i][j][r] = 0.f;

    const int NC = K / BKc;

    auto issue = [&](int chunk, int s) {
        const int k0 = chunk * BKc;
        #pragma unroll
        for (int i = 0; i < 4; ++i) {
            int c = tid + 128 * i;
            int row = c >> 2, c16 = c & 3;
            cp_async16(smU + s * STAGE_B + row * APITCH + c16 * 16,
                       (const char*)(A + (size_t)(bm + row) * K + k0) + c16 * 16, 16);
        }
        #pragma unroll
        for (int i = 0; i < 4; ++i) {
            int c = tid + 128 * i;
            int row = c >> 2, c16 = c & 3;
            int rn = bn + row;
            const char* g = (const char*)(W + (size_t)rn * K + k0) + c16 * 16;
            int sz = 16;
            if (rn >= N) { sz = 0; g = (const char*)W; }
            cp_async16(smU + s * STAGE_B + T128_B + row * APITCH + c16 * 16, g, sz);
        }
        CP_COMMIT();
    };

    const int wrow_off = ((lane >> 4) << 3) + (lane & 7);
    const int wcol_off = ((lane >> 3) & 1) * 8;
    const int arow_off = lane & 15;
    const int acol_off = (lane >> 4) << 3;

    auto compute = [&](int s) {
        const uint32_t aB = smU + s * STAGE_B;
        const uint32_t wB = aB + T128_B;
        #pragma unroll
        for (int ks = 0; ks < BKc; ks += 16) {
            uint32_t wh[4][4];
            #pragma unroll
            for (int nb = 0; nb < 4; ++nb)
                ldm_x4(wh[nb], wB + (wn + nb * 16 + wrow_off) * APITCH + (ks + wcol_off) * 2);
            #pragma unroll
            for (int mi = 0; mi < 4; ++mi) {
                uint32_t ah[4];
                ldm_x4(ah, aB + (wm + mi * 16 + arow_off) * APITCH + (ks + acol_off) * 2);
                #pragma unroll
                for (int nb = 0; nb < 4; ++nb) {
                    mma16816(&acc[mi][nb * 2][0],     ah, &wh[nb][0]);
                    mma16816(&acc[mi][nb * 2 + 1][0], ah, &wh[nb][2]);
                }
            }
        }
    };

    issue(0, 0);
    issue(1, 1);
    for (int c = 0; c < NC; ++c) {
        if (c + 1 < NC) { CP_WAIT(1); } else { CP_WAIT(0); }
        __syncthreads();
        if (c + 2 < NC) issue(c + 2, (c + 2) % 3);
        compute(c % 3);
    }

    float bs[16];
    #pragma unroll
    for (int nj = 0; nj < 8; ++nj) {
        int c0 = bn + wn + nj * 8 + (lane & 3) * 2;
        bs[nj * 2]     = (c0 < N)     ? bias[c0]     : 0.f;
        bs[nj * 2 + 1] = (c0 + 1 < N) ? bias[c0 + 1] : 0.f;
    }
    #pragma unroll
    for (int mi = 0; mi < 4; ++mi) {
        #pragma unroll
        for (int nj = 0; nj < 8; ++nj) {
            int c0 = bn + wn + nj * 8 + (lane & 3) * 2;
            if (c0 >= N) continue;
            #pragma unroll
            for (int p = 0; p < 2; ++p) {
                int row = bm + wm + mi * 16 + (lane >> 2) + p * 8;
                float v0 = acc[mi][nj][p * 2]     + bs[nj * 2];
                float v1 = acc[mi][nj][p * 2 + 1] + bs[nj * 2 + 1];
                if (mode == 0) {
                    *(float2*)(C + (size_t)row * N + c0) = make_float2(v0, v1);
                } else {
                    if (mode == 1) { v0 = fmaxf(v0, 0.f); v1 = fmaxf(v1, 0.f); }
                    *(__half2*)(Ch + (size_t)row * N + c0) = __floats2half2_rn(v0, v1);
                }
            }
        }
    }
}

// ================= batched tiny GEMM (all layers, float4 loads) =================
__global__ __launch_bounds__(256) void small_gemm_all(
    const float* __restrict__ A, int aStrideL,
    const float* __restrict__ W, size_t wStrideL,
    const float* __restrict__ bias, int biasStrideL,
    float* __restrict__ C)
{
    int wg   = blockIdx.x * 8 + (threadIdx.x >> 5);
    int lane = threadIdx.x & 31;
    if (wg >= Ll * Bb * Dd) return;
    int l  = wg / (Bb * Dd);
    int r  = wg - l * (Bb * Dd);
    int bq = r / Dd;
    int n  = r - bq * Dd;
    const float* a = A + (size_t)l * aStrideL + (size_t)bq * Dd;
    const float* w = W + (size_t)l * wStrideL + (size_t)n * Dd;
    float s = 0.f;
    #pragma unroll
    for (int i = 0; i < 6; ++i) {       // 6 * 128 = 768
        int k = lane * 4 + i * 128;
        float4 av = *(const float4*)&a[k];
        float4 wv = *(const float4*)&w[k];
        s = fmaf(av.x, wv.x, s);
        s = fmaf(av.y, wv.y, s);
        s = fmaf(av.z, wv.z, s);
        s = fmaf(av.w, wv.w, s);
    }
    #pragma unroll
    for (int o = 16; o; o >>= 1) s += __shfl_xor_sync(0xffffffffu, s, o);
    if (lane == 0) C[wg] = s + bias[(size_t)l * biasStrideL + n];
}

// ================= add+LN (ln3): 2 rows per 256-thread block (r10 optimum) ======
__global__ __launch_bounds__(256) void add_ln_kernel(
    float* __restrict__ x, const __half* __restrict__ y16,
    const float* __restrict__ g, const float* __restrict__ b,
    __half* __restrict__ x16)
{
    const int tid = threadIdx.x;
    const int grp = tid >> 7;
    const int t   = tid & 127;
    const int row = blockIdx.x * 2 + grp;
    const __half* yp = y16 + (size_t)row * Dd;
    float* xp = x + (size_t)row * Dd;
    __shared__ float sh1[2][4], sh2[2][4];
    const int w4   = (tid >> 5) & 3;
    const int lane = tid & 31;

    float v[6];
    float sum = 0.f, sq = 0.f;
    #pragma unroll
    for (int i = 0; i < 6; ++i) {
        int c = t + i * 128;
        float tt = xp[c] + __half2float(yp[c]);
        v[i] = tt; sum += tt; sq = fmaf(tt, tt, sq);
    }
    #pragma unroll
    for (int o = 16; o; o >>= 1) {
        sum += __shfl_xor_sync(0xffffffffu, sum, o);
        sq  += __shfl_xor_sync(0xffffffffu, sq,  o);
    }
    if (lane == 0) { sh1[grp][w4] = sum; sh2[grp][w4] = sq; }
    __syncthreads();
    if (t == 0) {
        float a = 0.f, c2 = 0.f;
        #pragma unroll
        for (int i = 0; i < 4; ++i) { a += sh1[grp][i]; c2 += sh2[grp][i]; }
        sh1[grp][0] = a; sh2[grp][0] = c2;
    }
    __syncthreads();
    float mu  = sh1[grp][0] * (1.f / Dd);
    float var = sh2[grp][0] * (1.f / Dd) - mu * mu;
    float rs  = rsqrtf(var + 1e-5f);
    #pragma unroll
    for (int i = 0; i < 6; ++i) {
        int c = t + i * 128;
        float o = (v[i] - mu) * rs * g[c] + b[c];
        xp[c] = o;
        x16[(size_t)row * Dd + c] = __float2half(o);
    }
}

// ================= fused (add+LN1)+(add bcast+LN2): 2 rows per block ===========
__global__ __launch_bounds__(256) void add_ln2_kernel(
    float* __restrict__ x, const __half* __restrict__ y16,
    const float* __restrict__ ca,
    const float* __restrict__ g1, const float* __restrict__ b1,
    const float* __restrict__ g2, const float* __restrict__ b2,
    __half* __restrict__ x16)
{
    const int tid = threadIdx.x;
    const int grp = tid >> 7;
    const int t   = tid & 127;
    const int row = blockIdx.x * 2 + grp;
    const __half* yp  = y16 + (size_t)row * Dd;
    const float* cap  = ca  + (size_t)(row >> 9) * Dd;
    float* xp = x + (size_t)row * Dd;
    __shared__ float sh1[2][4], sh2[2][4];
    const int w4   = (tid >> 5) & 3;
    const int lane = tid & 31;

    float v[6];
    float sum = 0.f, sq = 0.f;
    #pragma unroll
    for (int i = 0; i < 6; ++i) {
        int c = t + i * 128;
        float tt = xp[c] + __half2float(yp[c]);
        v[i] = tt; sum += tt; sq = fmaf(tt, tt, sq);
    }
    #pragma unroll
    for (int o = 16; o; o >>= 1) {
        sum += __shfl_xor_sync(0xffffffffu, sum, o);
        sq  += __shfl_xor_sync(0xffffffffu, sq,  o);
    }
    if (lane == 0) { sh1[grp][w4] = sum; sh2[grp][w4] = sq; }
    __syncthreads();
    if (t == 0) {
        float a = 0.f, c2 = 0.f;
        #pragma unroll
        for (int i = 0; i < 4; ++i) { a += sh1[grp][i]; c2 += sh2[grp][i]; }
        sh1[grp][0] = a; sh2[grp][0] = c2;
    }
    __syncthreads();
    float mu = sh1[grp][0] * (1.f / Dd);
    float rs = rsqrtf(sh2[grp][0] * (1.f / Dd) - mu * mu + 1e-5f);
    __syncthreads();

    sum = 0.f; sq = 0.f;
    #pragma unroll
    for (int i = 0; i < 6; ++i) {
        int c = t + i * 128;
        float tt = (v[i] - mu) * rs * g1[c] + b1[c] + cap[c];
        v[i] = tt; sum += tt; sq = fmaf(tt, tt, sq);
    }
    #pragma unroll
    for (int o = 16; o; o >>= 1) {
        sum += __shfl_xor_sync(0xffffffffu, sum, o);
        sq  += __shfl_xor_sync(0xffffffffu, sq,  o);
    }
    if (lane == 0) { sh1[grp][w4] = sum; sh2[grp][w4] = sq; }
    __syncthreads();
    if (t == 0) {
        float a = 0.f, c2 = 0.f;
        #pragma unroll
        for (int i = 0; i < 4; ++i) { a += sh1[grp][i]; c2 += sh2[grp][i]; }
        sh1[grp][0] = a; sh2[grp][0] = c2;
    }
    __syncthreads();
    float mu2 = sh1[grp][0] * (1.f / Dd);
    float rs2 = rsqrtf(sh2[grp][0] * (1.f / Dd) - mu2 * mu2 + 1e-5f);
    #pragma unroll
    for (int i = 0; i < 6; ++i) {
        int c = t + i * 128;
        float o = (v[i] - mu2) * rs2 * g2[c] + b2[c];
        xp[c] = o;
        x16[(size_t)row * Dd + c] = __float2half(o);
    }
}

// ================= flash-attention: 3-stage KV, long-first (r10 form, FROZEN) ===
#define FATT_SMEM 66560
#define QPITCH 208

__global__ void __launch_bounds__(256) attn_flash(
    const __half* __restrict__ qkv, __half* __restrict__ o16)
{
    extern __shared__ char smd[];
    const int bid  = blockIdx.x;
    const int qidx = (Ss/128 - 1) - (bid >> 7);   // longest blocks first
    const int rem  = bid & 127;
    const int h    = rem >> 4;
    const int b    = rem & 15;
    const int qb   = qidx * 128;
    const int tid  = threadIdx.x;
    const int lane = tid & 31;
    const int wid  = tid >> 5;
    const uint32_t sQ  = smem_u32(smd);
    const uint32_t sKV = sQ + 26624;
    const float scale2 = rsqrtf((float)DHd) * 1.4426950408889634f;

    #pragma unroll
    for (int i = 0; i < 6; ++i) {
        int c = tid + 256 * i;
        int row = c / 12, dc = c - row * 12;
        cp_async16(sQ + row * QPITCH + dc * 16,
                   qkv + (size_t)(b * Ss + qb + row) * QKVS + h * DHd + dc * 8, 16);
    }
    CP_COMMIT();

    auto load_kv = [&](int jt, int s) {
        #pragma unroll
        for (int i = 0; i < 3; ++i) {
            int c = tid + 256 * i;
            int kv = (c >= 384) ? 1 : 0;
            int cc = c - kv * 384;
            int row = cc / 12, dc = cc - row * 12;
            cp_async16(sKV + s * 13312 + kv * 6656 + row * QPITCH + dc * 16,
                       qkv + (size_t)(b * Ss + jt + row) * QKVS + (1 + kv) * Dd
                           + h * DHd + dc * 8, 16);
        }
        CP_COMMIT();
    };

    const int ntiles  = (qb + 128) / 32;
    load_kv(0, 0);
    load_kv(32, 1);
    CP_WAIT(2);
    __syncthreads();

    uint32_t qf[6][4];
    {
        uint32_t base = sQ + (wid * 16 + (lane & 15)) * QPITCH + ((lane >> 4) << 3) * 2;
        #pragma unroll
        for (int ks = 0; ks < 6; ++ks)
            ldm_x4(qf[ks], base + ks * 32);
    }

    float oacc[12][4];
    #pragma unroll
    for (int i = 0; i < 12; ++i)
        #pragma unroll
        for (int r = 0; r < 4; ++r) oacc[i][r] = 0.f;
    float m0 = -1e30f, m1 = -1e30f, l0 = 0.f, l1 = 0.f;

    const int my_last = qb + wid * 16 + 15;
    const int r0g     = qb + wid * 16 + (lane >> 2);

    for (int t = 0; t < ntiles; ++t) {
        const int jt = t * 32;
        if (t + 1 < ntiles) { CP_WAIT(1); } else { CP_WAIT(0); }
        __syncthreads();
        if (t + 2 < ntiles) load_kv((t + 2) * 32, (t + 2) % 3);

        if (jt <= my_last) {
            const uint32_t kb = sKV + (t % 3) * 13312;
            const uint32_t vb = kb + 6656;

            float sacc[4][4];
            #pragma unroll
            for (int i = 0; i < 4; ++i)
                #pragma unroll
                for (int r = 0; r < 4; ++r) sacc[i][r] = 0.f;
            const uint32_t kbase = kb + ((lane & 7) + ((lane >> 4) << 3)) * QPITCH
                                 + (((lane >> 3) & 1) << 4);
            #pragma unroll
            for (int ks = 0; ks < 6; ++ks) {
                uint32_t kf[4], kg[4];
                ldm_x4(kf, kbase + ks * 32);
                ldm_x4(kg, kbase + 16 * QPITCH + ks * 32);
                mma16816(sacc[0], qf[ks], &kf[0]);
                mma16816(sacc[1], qf[ks], &kf[2]);
                mma16816(sacc[2], qf[ks], &kg[0]);
                mma16816(sacc[3], qf[ks], &kg[2]);
            }

            #pragma unroll
            for (int nb = 0; nb < 4; ++nb)
                #pragma unroll
                for (int e = 0; e < 4; ++e) {
                    int j = jt + nb * 8 + (lane & 3) * 2 + (e & 1);
                    int r = r0g + ((e >> 1) << 3);
                    float v = sacc[nb][e] * scale2;
                    sacc[nb][e] = (j <= r) ? v : -1e30f;
                }

            float mx0 = -1e30f, mx1 = -1e30f;
            #pragma unroll
            for (int nb = 0; nb < 4; ++nb) {
                mx0 = fmaxf(mx0, fmaxf(sacc[nb][0], sacc[nb][1]));
                mx1 = fmaxf(mx1, fmaxf(sacc[nb][2], sacc[nb][3]));
            }
            mx0 = fmaxf(mx0, __shfl_xor_sync(0xffffffffu, mx0, 1));
            mx0 = fmaxf(mx0, __shfl_xor_sync(0xffffffffu, mx0, 2));
            mx1 = fmaxf(mx1, __shfl_xor_sync(0xffffffffu, mx1, 1));
            mx1 = fmaxf(mx1, __shfl_xor_sync(0xffffffffu, mx1, 2));
            float mn0 = fmaxf(m0, mx0), mn1 = fmaxf(m1, mx1);

            if (__any_sync(0xffffffffu, (mn0 > m0) || (mn1 > m1))) {
                float f0 = ex2(m0 - mn0), f1 = ex2(m1 - mn1);
                l0 *= f0; l1 *= f1;
                #pragma unroll
                for (int c6 = 0; c6 < 12; ++c6) {
                    oacc[c6][0] *= f0; oacc[c6][1] *= f0;
                    oacc[c6][2] *= f1; oacc[c6][3] *= f1;
                }
            }
            m0 = mn0; m1 = mn1;

            float s0 = 0.f, s1 = 0.f;
            #pragma unroll
            for (int nb = 0; nb < 4; ++nb) {
                float p0 = ex2(sacc[nb][0] - mn0);
                float p1 = ex2(sacc[nb][1] - mn0);
                float p2 = ex2(sacc[nb][2] - mn1);
                float p3 = ex2(sacc[nb][3] - mn1);
                sacc[nb][0] = p0; sacc[nb][1] = p1;
                sacc[nb][2] = p2; sacc[nb][3] = p3;
                s0 += p0 + p1; s1 += p2 + p3;
            }
            s0 += __shfl_xor_sync(0xffffffffu, s0, 1);
            s0 += __shfl_xor_sync(0xffffffffu, s0, 2);
            s1 += __shfl_xor_sync(0xffffffffu, s1, 1);
            s1 += __shfl_xor_sync(0xffffffffu, s1, 2);
            l0 += s0;
            l1 += s1;

            uint32_t pa[2][4];
            #pragma unroll
            for (int kk = 0; kk < 2; ++kk) {
                pa[kk][0] = pack_h2(sacc[kk*2][0],   sacc[kk*2][1]);
                pa[kk][1] = pack_h2(sacc[kk*2][2],   sacc[kk*2][3]);
                pa[kk][2] = pack_h2(sacc[kk*2+1][0], sacc[kk*2+1][1]);
                pa[kk][3] = pack_h2(sacc[kk*2+1][2], sacc[kk*2+1][3]);
            }

            const uint32_t vrow = vb + ((lane & 7) + (((lane >> 3) & 1) << 3)) * QPITCH;
            #pragma unroll
            for (int kk = 0; kk < 2; ++kk) {
                #pragma unroll
                for (int c6 = 0; c6 < 6; ++c6) {
                    uint32_t vf[4];
                    ldm_trans_x4(vf, vrow + kk * 16 * QPITCH
                                     + (c6 * 16 + ((lane >> 4) << 3)) * 2);
                    mma16816(oacc[c6 * 2],     pa[kk], &vf[0]);
                    mma16816(oacc[c6 * 2 + 1], pa[kk], &vf[2]);
                }
            }
        }
    }

    float il0 = 1.f / l0, il1 = 1.f / l1;
    #pragma unroll
    for (int c6 = 0; c6 < 12; ++c6) {
        int col = h * DHd + c6 * 8 + (lane & 3) * 2;
        *(__half2*)(o16 + (size_t)(b * Ss + r0g) * Dd + col) =
            __floats2half2_rn(oacc[c6][0] * il0, oacc[c6][1] * il0);
        *(__half2*)(o16 + (size_t)(b * Ss + r0g + 8) * Dd + col) =
            __floats2half2_rn(oacc[c6][2] * il1, oacc[c6][3] * il1);
    }
}

// ================= launcher =================
extern "C" void kernel_launch(void* const* d_in, const int* in_sizes, int n_in,
                              void* d_out, int out_size)
{
    (void)in_sizes; (void)n_in; (void)out_size;
    const float* latent   = (const float*)d_in[0];
    const int*   target   = (const int*)  d_in[1];
    const float* tok_emb  = (const float*)d_in[2];
    const float* pos_emb  = (const float*)d_in[3];
    const float* sa_w_qkv = (const float*)d_in[4];
    const float* sa_b_qkv = (const float*)d_in[5];
    const float* sa_w_o   = (const float*)d_in[6];
    const float* sa_b_o   = (const float*)d_in[7];
    const float* ca_w_qkv = (const float*)d_in[8];
    const float* ca_b_qkv = (const float*)d_in[9];
    const float* ca_w_o   = (const float*)d_in[10];
    const float* ca_b_o   = (const float*)d_in[11];
    const float* ffn_w1   = (const float*)d_in[12];
    const float* ffn_b1   = (const float*)d_in[13];
    const float* ffn_w2   = (const float*)d_in[14];
    const float* ffn_b2   = (const float*)d_in[15];
    const float* ln1_g    = (const float*)d_in[16];
    const float* ln1_b    = (const float*)d_in[17];
    const float* ln2_g    = (const float*)d_in[18];
    const float* ln2_b    = (const float*)d_in[19];
    const float* ln3_g    = (const float*)d_in[20];
    const float* ln3_b    = (const float*)d_in[21];
    const float* out_w    = (const float*)d_in[22];
    const float* out_b    = (const float*)d_in[23];

    float *x, *cat, *ca;
    __half *x16, *o16, *y16, *h16, *qkv16, *wqkv16, *wo16, *w116, *w216, *wout16;
    cudaGetSymbolAddress((void**)&x,   g_x);
    cudaGetSymbolAddress((void**)&cat, g_cat);
    cudaGetSymbolAddress((void**)&ca,  g_ca);
    cudaGetSymbolAddress((void**)&x16, g_x16);
    cudaGetSymbolAddress((void**)&o16, g_o16);
    cudaGetSymbolAddress((void**)&y16, g_y16);
    cudaGetSymbolAddress((void**)&h16, g_h16);
    cudaGetSymbolAddress((void**)&qkv16, g_qkv16);
    cudaGetSymbolAddress((void**)&wqkv16, g_wqkv16);
    cudaGetSymbolAddress((void**)&wo16,   g_wo16);
    cudaGetSymbolAddress((void**)&w116,   g_w116);
    cudaGetSymbolAddress((void**)&w216,   g_w216);
    cudaGetSymbolAddress((void**)&wout16, g_wout16);

    cudaFuncSetAttribute(gemm_fp16,  cudaFuncAttributeMaxDynamicSharedMemorySize, GEMM_SMEM);
    cudaFuncSetAttribute(attn_flash, cudaFuncAttributeMaxDynamicSharedMemorySize, FATT_SMEM);

    // 0: weight conversions
    const int nb0 = (Ll*3*Dd*Dd) / 1024, nb1 = (Ll*Dd*Dd) / 1024,
              nb2 = (Ll*Ff*Dd) / 1024,   nb3 = (Ll*Dd*Ff) / 1024,
              nb4 = (Vv*Dd) / 1024;
    convert_all<<<nb0 + nb1 + nb2 + nb3 + nb4, 256>>>(
        sa_w_qkv, wqkv16, nb0, sa_w_o, wo16, nb1,
        ffn_w1, w116, nb2, ffn_w2, w216, nb3, out_w, wout16, nb4);

    // 1: embed (vectorized)
    embed_kernel<<<Mm, 192>>>(target, tok_emb, pos_emb, x, x16);

    // 2: batched cross-attn stage-1
    const int SGB = (Ll * Bb * Dd) / 8;
    small_gemm_all<<<SGB, 256>>>(
        latent, 0,
        ca_w_qkv + (size_t)2*Dd*Dd, (size_t)3*Dd*Dd,
        ca_b_qkv + 2*Dd, 3*Dd, cat);

    // 3: QKV gemm (layer 0), 4: attention (512 CTAs, long-first), 5: O-proj
    gemm_fp16<<<dim3(18, 64), 128, GEMM_SMEM>>>(
        x16, wqkv16, sa_b_qkv, nullptr, qkv16, Mm, QKVS, Dd, 2);
    attn_flash<<<512, 256, FATT_SMEM>>>(qkv16, o16);
    gemm_fp16<<<dim3(6, 64), 128, GEMM_SMEM>>>(
        o16, wo16, sa_b_o, nullptr, y16, Mm, Dd, Dd, 2);

    // 6: batched cross-attn stage-2
    small_gemm_all<<<SGB, 256>>>(
        cat, Bb*Dd,
        ca_w_o, (size_t)Dd*Dd,
        ca_b_o, Dd, ca);

    for (int l = 0; l < Ll; ++l) {
        if (l > 0) {
            gemm_fp16<<<dim3(18, 64), 128, GEMM_SMEM>>>(
                x16, wqkv16 + (size_t)l*3*Dd*Dd, sa_b_qkv + (size_t)l*3*Dd,
                nullptr, qkv16, Mm, QKVS, Dd, 2);
            attn_flash<<<512, 256, FATT_SMEM>>>(qkv16, o16);
            gemm_fp16<<<dim3(6, 64), 128, GEMM_SMEM>>>(
                o16, wo16 + (size_t)l*Dd*Dd, sa_b_o + (size_t)l*Dd,
                nullptr, y16, Mm, Dd, Dd, 2);
        }
        add_ln2_kernel<<<Mm/2, 256>>>(x, y16, ca + l*Bb*Dd,
                                      ln1_g + (size_t)l*Dd, ln1_b + (size_t)l*Dd,
                                      ln2_g + (size_t)l*Dd, ln2_b + (size_t)l*Dd, x16);
        gemm_fp16<<<dim3(16, 64), 128, GEMM_SMEM>>>(
            x16, w116 + (size_t)l*Ff*Dd, ffn_b1 + (size_t)l*Ff,
            nullptr, h16, Mm, Ff, Dd, 1);
        gemm_fp16<<<dim3(6, 64), 128, GEMM_SMEM>>>(
            h16, w216 + (size_t)l*Dd*Ff, ffn_b2 + (size_t)l*Dd,
            nullptr, y16, Mm, Dd, Ff, 2);
        add_ln_kernel<<<Mm/2, 256>>>(x, y16, ln3_g + (size_t)l*Dd, ln3_b + (size_t)l*Dd,
                                     x16);
    }

    // output projection (fp32 out)
    gemm_fp16<<<dim3(1, 64), 128, GEMM_SMEM>>>(
        x16, wout16, out_b, (float*)d_out, nullptr, Mm, Vv, Dd, 0);
}

// round 15
// speedup vs baseline: 1.0486x; 1.0027x over previous
#include <cuda_runtime.h>
#include <cuda_fp16.h>
#include <stdint.h>
#include <math.h>

// Problem dims
#define Bb   16
#define Ss   512
#define Dd   768
#define Hh   8
#define Vv   100
#define Ff   2048
#define Ll   6
#define DHd  96
#define Mm   (Bb*Ss)   // 8192
#define QKVS (3*Dd)    // 2304

// ================= low-level helpers =================
__device__ __forceinline__ uint32_t smem_u32(const void* p) {
    return (uint32_t)__cvta_generic_to_shared(p);
}
__device__ __forceinline__ void cp_async16(uint32_t dst, const void* src, int szvalid) {
    asm volatile("cp.async.cg.shared.global [%0], [%1], 16, %2;"
                 :: "r"(dst), "l"(src), "r"(szvalid) : "memory");
}
#define CP_COMMIT() asm volatile("cp.async.commit_group;" ::: "memory")
#define CP_WAIT(n)  asm volatile("cp.async.wait_group %0;" :: "n"(n) : "memory")

__device__ __forceinline__ void ldm_x4(uint32_t* r, uint32_t addr) {
    asm volatile("ldmatrix.sync.aligned.m8n8.x4.shared.b16 {%0,%1,%2,%3}, [%4];"
                 : "=r"(r[0]), "=r"(r[1]), "=r"(r[2]), "=r"(r[3]) : "r"(addr));
}
__device__ __forceinline__ void ldm_trans_x4(uint32_t* r, uint32_t addr) {
    asm volatile("ldmatrix.sync.aligned.m8n8.x4.trans.shared.b16 {%0,%1,%2,%3}, [%4];"
                 : "=r"(r[0]), "=r"(r[1]), "=r"(r[2]), "=r"(r[3]) : "r"(addr));
}
__device__ __forceinline__ void mma16816(float* d, const uint32_t* a, const uint32_t* b) {
    asm volatile("mma.sync.aligned.m16n8k16.row.col.f32.f16.f16.f32 "
                 "{%0,%1,%2,%3}, {%4,%5,%6,%7}, {%8,%9}, {%0,%1,%2,%3};"
                 : "+f"(d[0]), "+f"(d[1]), "+f"(d[2]), "+f"(d[3])
                 : "r"(a[0]), "r"(a[1]), "r"(a[2]), "r"(a[3]), "r"(b[0]), "r"(b[1]));
}
__device__ __forceinline__ uint32_t pack_h2(float a, float b) {
    __half2 t = __floats2half2_rn(a, b);
    return *(uint32_t*)&t;
}
__device__ __forceinline__ float ex2(float x) {
    float y;
    asm("ex2.approx.f32 %0, %1;" : "=f"(y) : "f"(x));
    return y;
}

// ================= device scratch =================
__device__ float g_x   [Mm * Dd];
__device__ float g_cat [Ll * Bb * Dd];
__device__ float g_ca  [Ll * Bb * Dd];
__device__ float g_part[3 * Mm * Vv];    // split-K partials for out-proj

__device__ __align__(16) __half g_x16 [Mm * Dd];
__device__ __align__(16) __half g_o16 [Mm * Dd];
__device__ __align__(16) __half g_y16 [Mm * Dd];
__device__ __align__(16) __half g_h16 [Mm * Ff];
__device__ __align__(16) __half g_qkv16[Mm * QKVS];

__device__ __align__(16) __half g_wqkv16[Ll*3*Dd*Dd];
__device__ __align__(16) __half g_wo16  [Ll*Dd*Dd];
__device__ __align__(16) __half g_w116  [Ll*Ff*Dd];
__device__ __align__(16) __half g_w216  [Ll*Dd*Ff];
__device__ __align__(16) __half g_wout16[Vv*Dd];

// ================= weight convert: 16 floats/thread (MLP=4) =================
__global__ __launch_bounds__(256) void convert_all(
    const float* __restrict__ s0, __half* __restrict__ d0, int b0,
    const float* __restrict__ s1, __half* __restrict__ d1, int b1,
    const float* __restrict__ s2, __half* __restrict__ d2, int b2,
    const float* __restrict__ s3, __half* __restrict__ d3, int b3,
    const float* __restrict__ s4, __half* __restrict__ d4, int b4)
{
    int bid = blockIdx.x;
    const float* src; __half* dst; int nb;
    if      (bid < b0)          { src = s0; dst = d0; nb = bid; }
    else if (bid < b0+b1)       { src = s1; dst = d1; nb = bid - b0; }
    else if (bid < b0+b1+b2)    { src = s2; dst = d2; nb = bid - b0 - b1; }
    else if (bid < b0+b1+b2+b3) { src = s3; dst = d3; nb = bid - b0 - b1 - b2; }
    else                        { src = s4; dst = d4; nb = bid - b0 - b1 - b2 - b3; }
    // block covers 256 threads * 16 floats = 4096 floats
    int base = nb * 4096 + threadIdx.x * 4;
    float4 v0 = *(const float4*)&src[base];
    float4 v1 = *(const float4*)&src[base + 1024];
    float4 v2 = *(const float4*)&src[base + 2048];
    float4 v3 = *(const float4*)&src[base + 3072];
    *(__half2*)&dst[base]            = __floats2half2_rn(v0.x, v0.y);
    *(__half2*)&dst[base + 2]        = __floats2half2_rn(v0.z, v0.w);
    *(__half2*)&dst[base + 1024]     = __floats2half2_rn(v1.x, v1.y);
    *(__half2*)&dst[base + 1026]     = __floats2half2_rn(v1.z, v1.w);
    *(__half2*)&dst[base + 2048]     = __floats2half2_rn(v2.x, v2.y);
    *(__half2*)&dst[base + 2050]     = __floats2half2_rn(v2.z, v2.w);
    *(__half2*)&dst[base + 3072]     = __floats2half2_rn(v3.x, v3.y);
    *(__half2*)&dst[base + 3074]     = __floats2half2_rn(v3.z, v3.w);
}

// ================= embed (vectorized: 192 threads x float4) =================
__global__ __launch_bounds__(192) void embed_kernel(
    const int* __restrict__ target, const float* __restrict__ tok,
    const float* __restrict__ pos, float* __restrict__ x,
    __half* __restrict__ x16)
{
    int row = blockIdx.x;
    int s   = row & (Ss - 1);
    int t   = target[row];
    const float* tp = tok + (size_t)t * Dd;
    const float* pp = pos + (size_t)s * Dd;
    size_t base = (size_t)row * Dd;
    int c = threadIdx.x * 4;
    float4 a = *(const float4*)&tp[c];
    float4 p = *(const float4*)&pp[c];
    float4 v = make_float4(a.x + p.x, a.y + p.y, a.z + p.z, a.w + p.w);
    *(float4*)&x[base + c] = v;
    *(__half2*)&x16[base + c]     = __floats2half2_rn(v.x, v.y);
    *(__half2*)&x16[base + c + 2] = __floats2half2_rn(v.z, v.w);
}

// ================= fp16 GEMM: CTA 128x128, 4 warps, 3-stage (FROZEN) =========
#define BKc 32
#define APITCH 80
#define T128_B   (128*APITCH)
#define STAGE_B  (2*T128_B)
#define GEMM_SMEM (3*STAGE_B)

__global__ void __launch_bounds__(128, 3) gemm_fp16(
    const __half* __restrict__ A, const __half* __restrict__ W,
    const float* __restrict__ bias, float* __restrict__ C,
    __half* __restrict__ Ch,
    int M, int N, int K, int mode)
{
    extern __shared__ char sm[];
    const uint32_t smU = smem_u32(sm);
    const int tid  = threadIdx.x;
    const int lane = tid & 31;
    const int wid  = tid >> 5;
    const int bm   = blockIdx.y * 128;
    const int bn   = blockIdx.x * 128;
    const int wm   = (wid >> 1) * 64;
    const int wn   = (wid & 1) * 64;

    float acc[4][8][4];
    #pragma unroll
    for (int i = 0; i < 4; ++i)
        #pragma unroll
        for (int j = 0; j < 8; ++j)
            #pragma unroll
            for (int r = 0; r < 4; ++r) acc[i][j][r] = 0.f;

    const int NC = K / BKc;

    auto issue = [&](int chunk, int s) {
        const int k0 = chunk * BKc;
        #pragma unroll
        for (int i = 0; i < 4; ++i) {
            int c = tid + 128 * i;
            int row = c >> 2, c16 = c & 3;
            cp_async16(smU + s * STAGE_B + row * APITCH + c16 * 16,
                       (const char*)(A + (size_t)(bm + row) * K + k0) + c16 * 16, 16);
        }
        #pragma unroll
        for (int i = 0; i < 4; ++i) {
            int c = tid + 128 * i;
            int row = c >> 2, c16 = c & 3;
            int rn = bn + row;
            const char* g = (const char*)(W + (size_t)rn * K + k0) + c16 * 16;
            int sz = 16;
            if (rn >= N) { sz = 0; g = (const char*)W; }
            cp_async16(smU + s * STAGE_B + T128_B + row * APITCH + c16 * 16, g, sz);
        }
        CP_COMMIT();
    };

    const int wrow_off = ((lane >> 4) << 3) + (lane & 7);
    const int wcol_off = ((lane >> 3) & 1) * 8;
    const int arow_off = lane & 15;
    const int acol_off = (lane >> 4) << 3;

    auto compute = [&](int s) {
        const uint32_t aB = smU + s * STAGE_B;
        const uint32_t wB = aB + T128_B;
        #pragma unroll
        for (int ks = 0; ks < BKc; ks += 16) {
            uint32_t wh[4][4];
            #pragma unroll
            for (int nb = 0; nb < 4; ++nb)
                ldm_x4(wh[nb], wB + (wn + nb * 16 + wrow_off) * APITCH + (ks + wcol_off) * 2);
            #pragma unroll
            for (int mi = 0; mi < 4; ++mi) {
                uint32_t ah[4];
                ldm_x4(ah, aB + (wm + mi * 16 + arow_off) * APITCH + (ks + acol_off) * 2);
                #pragma unroll
                for (int nb = 0; nb < 4; ++nb) {
                    mma16816(&acc[mi][nb * 2][0],     ah, &wh[nb][0]);
                    mma16816(&acc[mi][nb * 2 + 1][0], ah, &wh[nb][2]);
                }
            }
        }
    };

    issue(0, 0);
    issue(1, 1);
    for (int c = 0; c < NC; ++c) {
        if (c + 1 < NC) { CP_WAIT(1); } else { CP_WAIT(0); }
        __syncthreads();
        if (c + 2 < NC) issue(c + 2, (c + 2) % 3);
        compute(c % 3);
    }

    float bs[16];
    #pragma unroll
    for (int nj = 0; nj < 8; ++nj) {
        int c0 = bn + wn + nj * 8 + (lane & 3) * 2;
        bs[nj * 2]     = (c0 < N)     ? bias[c0]     : 0.f;
        bs[nj * 2 + 1] = (c0 + 1 < N) ? bias[c0 + 1] : 0.f;
    }
    #pragma unroll
    for (int mi = 0; mi < 4; ++mi) {
        #pragma unroll
        for (int nj = 0; nj < 8; ++nj) {
            int c0 = bn + wn + nj * 8 + (lane & 3) * 2;
            if (c0 >= N) continue;
            #pragma unroll
            for (int p = 0; p < 2; ++p) {
                int row = bm + wm + mi * 16 + (lane >> 2) + p * 8;
                float v0 = acc[mi][nj][p * 2]     + bs[nj * 2];
                float v1 = acc[mi][nj][p * 2 + 1] + bs[nj * 2 + 1];
                if (mode == 0) {
                    *(float2*)(C + (size_t)row * N + c0) = make_float2(v0, v1);
                } else {
                    if (mode == 1) { v0 = fmaxf(v0, 0.f); v1 = fmaxf(v1, 0.f); }
                    *(__half2*)(Ch + (size_t)row * N + c0) = __floats2half2_rn(v0, v1);
                }
            }
        }
    }
}

// ================= split-K GEMM for out-proj (copy; fp32 partials, no bias) =====
// blockIdx.z = K partition (Kpart deep); A row stride = Klda.
__global__ void __launch_bounds__(128, 3) gemm_fp16_sk(
    const __half* __restrict__ A, const __half* __restrict__ W,
    float* __restrict__ P,
    int M, int N, int Kpart, int Klda)
{
    extern __shared__ char sm[];
    const uint32_t smU = smem_u32(sm);
    const int tid  = threadIdx.x;
    const int lane = tid & 31;
    const int wid  = tid >> 5;
    const int bm   = blockIdx.y * 128;
    const int bn   = blockIdx.x * 128;
    const int kz   = blockIdx.z * Kpart;
    const int wm   = (wid >> 1) * 64;
    const int wn   = (wid & 1) * 64;
    float* C = P + (size_t)blockIdx.z * M * N;

    float acc[4][8][4];
    #pragma unroll
    for (int i = 0; i < 4; ++i)
        #pragma unroll
        for (int j = 0; j < 8; ++j)
            #pragma unroll
            for (int r = 0; r < 4; ++r) acc[i][j][r] = 0.f;

    const int NC = Kpart / BKc;

    auto issue = [&](int chunk, int s) {
        const int k0 = kz + chunk * BKc;
        #pragma unroll
        for (int i = 0; i < 4; ++i) {
            int c = tid + 128 * i;
            int row = c >> 2, c16 = c & 3;
            cp_async16(smU + s * STAGE_B + row * APITCH + c16 * 16,
                       (const char*)(A + (size_t)(bm + row) * Klda + k0) + c16 * 16, 16);
        }
        #pragma unroll
        for (int i = 0; i < 4; ++i) {
            int c = tid + 128 * i;
            int row = c >> 2, c16 = c & 3;
            int rn = bn + row;
            const char* g = (const char*)(W + (size_t)rn * Klda + k0) + c16 * 16;
            int sz = 16;
            if (rn >= N) { sz = 0; g = (const char*)W; }
            cp_async16(smU + s * STAGE_B + T128_B + row * APITCH + c16 * 16, g, sz);
        }
        CP_COMMIT();
    };

    const int wrow_off = ((lane >> 4) << 3) + (lane & 7);
    const int wcol_off = ((lane >> 3) & 1) * 8;
    const int arow_off = lane & 15;
    const int acol_off = (lane >> 4) << 3;

    auto compute = [&](int s) {
        const uint32_t aB = smU + s * STAGE_B;
        const uint32_t wB = aB + T128_B;
        #pragma unroll
        for (int ks = 0; ks < BKc; ks += 16) {
            uint32_t wh[4][4];
            #pragma unroll
            for (int nb = 0; nb < 4; ++nb)
                ldm_x4(wh[nb], wB + (wn + nb * 16 + wrow_off) * APITCH + (ks + wcol_off) * 2);
            #pragma unroll
            for (int mi = 0; mi < 4; ++mi) {
                uint32_t ah[4];
                ldm_x4(ah, aB + (wm + mi * 16 + arow_off) * APITCH + (ks + acol_off) * 2);
                #pragma unroll
                for (int nb = 0; nb < 4; ++nb) {
                    mma16816(&acc[mi][nb * 2][0],     ah, &wh[nb][0]);
                    mma16816(&acc[mi][nb * 2 + 1][0], ah, &wh[nb][2]);
                }
            }
        }
    };

    issue(0, 0);
    issue(1, 1);
    for (int c = 0; c < NC; ++c) {
        if (c + 1 < NC) { CP_WAIT(1); } else { CP_WAIT(0); }
        __syncthreads();
        if (c + 2 < NC) issue(c + 2, (c + 2) % 3);
        compute(c % 3);
    }

    #pragma unroll
    for (int mi = 0; mi < 4; ++mi) {
        #pragma unroll
        for (int nj = 0; nj < 8; ++nj) {
            int c0 = bn + wn + nj * 8 + (lane & 3) * 2;
            if (c0 >= N) continue;
            #pragma unroll
            for (int p = 0; p < 2; ++p) {
                int row = bm + wm + mi * 16 + (lane >> 2) + p * 8;
                *(float2*)(C + (size_t)row * N + c0) =
                    make_float2(acc[mi][nj][p * 2], acc[mi][nj][p * 2 + 1]);
            }
        }
    }
}

// ================= split-K reduce + bias =================
__global__ __launch_bounds__(256) void sk_reduce(
    const float* __restrict__ P, const float* __restrict__ bias,
    float* __restrict__ out)
{
    int i = blockIdx.x * 256 + threadIdx.x;
    if (i >= Mm * Vv) return;
    int col = i % Vv;
    out[i] = P[i] + P[i + Mm * Vv] + P[i + 2 * Mm * Vv] + bias[col];
}

// ================= batched tiny GEMM (all layers, float4 loads) =================
__global__ __launch_bounds__(256) void small_gemm_all(
    const float* __restrict__ A, int aStrideL,
    const float* __restrict__ W, size_t wStrideL,
    const float* __restrict__ bias, int biasStrideL,
    float* __restrict__ C)
{
    int wg   = blockIdx.x * 8 + (threadIdx.x >> 5);
    int lane = threadIdx.x & 31;
    if (wg >= Ll * Bb * Dd) return;
    int l  = wg / (Bb * Dd);
    int r  = wg - l * (Bb * Dd);
    int bq = r / Dd;
    int n  = r - bq * Dd;
    const float* a = A + (size_t)l * aStrideL + (size_t)bq * Dd;
    const float* w = W + (size_t)l * wStrideL + (size_t)n * Dd;
    float s = 0.f;
    #pragma unroll
    for (int i = 0; i < 6; ++i) {
        int k = lane * 4 + i * 128;
        float4 av = *(const float4*)&a[k];
        float4 wv = *(const float4*)&w[k];
        s = fmaf(av.x, wv.x, s);
        s = fmaf(av.y, wv.y, s);
        s = fmaf(av.z, wv.z, s);
        s = fmaf(av.w, wv.w, s);
    }
    #pragma unroll
    for (int o = 16; o; o >>= 1) s += __shfl_xor_sync(0xffffffffu, s, o);
    if (lane == 0) C[wg] = s + bias[(size_t)l * biasStrideL + n];
}

// ================= add+LN (ln3): 2 rows per 256-thread block =================
__global__ __launch_bounds__(256) void add_ln_kernel(
    float* __restrict__ x, const __half* __restrict__ y16,
    const float* __restrict__ g, const float* __restrict__ b,
    __half* __restrict__ x16)
{
    const int tid = threadIdx.x;
    const int grp = tid >> 7;
    const int t   = tid & 127;
    const int row = blockIdx.x * 2 + grp;
    const __half* yp = y16 + (size_t)row * Dd;
    float* xp = x + (size_t)row * Dd;
    __shared__ float sh1[2][4], sh2[2][4];
    const int w4   = (tid >> 5) & 3;
    const int lane = tid & 31;

    float v[6];
    float sum = 0.f, sq = 0.f;
    #pragma unroll
    for (int i = 0; i < 6; ++i) {
        int c = t + i * 128;
        float tt = xp[c] + __half2float(yp[c]);
        v[i] = tt; sum += tt; sq = fmaf(tt, tt, sq);
    }
    #pragma unroll
    for (int o = 16; o; o >>= 1) {
        sum += __shfl_xor_sync(0xffffffffu, sum, o);
        sq  += __shfl_xor_sync(0xffffffffu, sq,  o);
    }
    if (lane == 0) { sh1[grp][w4] = sum; sh2[grp][w4] = sq; }
    __syncthreads();
    if (t == 0) {
        float a = 0.f, c2 = 0.f;
        #pragma unroll
        for (int i = 0; i < 4; ++i) { a += sh1[grp][i]; c2 += sh2[grp][i]; }
        sh1[grp][0] = a; sh2[grp][0] = c2;
    }
    __syncthreads();
    float mu  = sh1[grp][0] * (1.f / Dd);
    float var = sh2[grp][0] * (1.f / Dd) - mu * mu;
    float rs  = rsqrtf(var + 1e-5f);
    #pragma unroll
    for (int i = 0; i < 6; ++i) {
        int c = t + i * 128;
        float o = (v[i] - mu) * rs * g[c] + b[c];
        xp[c] = o;
        x16[(size_t)row * Dd + c] = __float2half(o);
    }
}

// ================= fused (add+LN1)+(add bcast+LN2): 2 rows per block ===========
__global__ __launch_bounds__(256) void add_ln2_kernel(
    float* __restrict__ x, const __half* __restrict__ y16,
    const float* __restrict__ ca,
    const float* __restrict__ g1, const float* __restrict__ b1,
    const float* __restrict__ g2, const float* __restrict__ b2,
    __half* __restrict__ x16)
{
    const int tid = threadIdx.x;
    const int grp = tid >> 7;
    const int t   = tid & 127;
    const int row = blockIdx.x * 2 + grp;
    const __half* yp  = y16 + (size_t)row * Dd;
    const float* cap  = ca  + (size_t)(row >> 9) * Dd;
    float* xp = x + (size_t)row * Dd;
    __shared__ float sh1[2][4], sh2[2][4];
    const int w4   = (tid >> 5) & 3;
    const int lane = tid & 31;

    float v[6];
    float sum = 0.f, sq = 0.f;
    #pragma unroll
    for (int i = 0; i < 6; ++i) {
        int c = t + i * 128;
        float tt = xp[c] + __half2float(yp[c]);
        v[i] = tt; sum += tt; sq = fmaf(tt, tt, sq);
    }
    #pragma unroll
    for (int o = 16; o; o >>= 1) {
        sum += __shfl_xor_sync(0xffffffffu, sum, o);
        sq  += __shfl_xor_sync(0xffffffffu, sq,  o);
    }
    if (lane == 0) { sh1[grp][w4] = sum; sh2[grp][w4] = sq; }
    __syncthreads();
    if (t == 0) {
        float a = 0.f, c2 = 0.f;
        #pragma unroll
        for (int i = 0; i < 4; ++i) { a += sh1[grp][i]; c2 += sh2[grp][i]; }
        sh1[grp][0] = a; sh2[grp][0] = c2;
    }
    __syncthreads();
    float mu = sh1[grp][0] * (1.f / Dd);
    float rs = rsqrtf(sh2[grp][0] * (1.f / Dd) - mu * mu + 1e-5f);
    __syncthreads();

    sum = 0.f; sq = 0.f;
    #pragma unroll
    for (int i = 0; i < 6; ++i) {
        int c = t + i * 128;
        float tt = (v[i] - mu) * rs * g1[c] + b1[c] + cap[c];
        v[i] = tt; sum += tt; sq = fmaf(tt, tt, sq);
    }
    #pragma unroll
    for (int o = 16; o; o >>= 1) {
        sum += __shfl_xor_sync(0xffffffffu, sum, o);
        sq  += __shfl_xor_sync(0xffffffffu, sq,  o);
    }
    if (lane == 0) { sh1[grp][w4] = sum; sh2[grp][w4] = sq; }
    __syncthreads();
    if (t == 0) {
        float a = 0.f, c2 = 0.f;
        #pragma unroll
        for (int i = 0; i < 4; ++i) { a += sh1[grp][i]; c2 += sh2[grp][i]; }
        sh1[grp][0] = a; sh2[grp][0] = c2;
    }
    __syncthreads();
    float mu2 = sh1[grp][0] * (1.f / Dd);
    float rs2 = rsqrtf(sh2[grp][0] * (1.f / Dd) - mu2 * mu2 + 1e-5f);
    #pragma unroll
    for (int i = 0; i < 6; ++i) {
        int c = t + i * 128;
        float o = (v[i] - mu2) * rs2 * g2[c] + b2[c];
        xp[c] = o;
        x16[(size_t)row * Dd + c] = __float2half(o);
    }
}

// ================= flash-attention: 3-stage KV, long-first (FROZEN) =============
#define FATT_SMEM 66560
#define QPITCH 208

__global__ void __launch_bounds__(256) attn_flash(
    const __half* __restrict__ qkv, __half* __restrict__ o16)
{
    extern __shared__ char smd[];
    const int bid  = blockIdx.x;
    const int qidx = (Ss/128 - 1) - (bid >> 7);
    const int rem  = bid & 127;
    const int h    = rem >> 4;
    const int b    = rem & 15;
    const int qb   = qidx * 128;
    const int tid  = threadIdx.x;
    const int lane = tid & 31;
    const int wid  = tid >> 5;
    const uint32_t sQ  = smem_u32(smd);
    const uint32_t sKV = sQ + 26624;
    const float scale2 = rsqrtf((float)DHd) * 1.4426950408889634f;

    #pragma unroll
    for (int i = 0; i < 6; ++i) {
        int c = tid + 256 * i;
        int row = c / 12, dc = c - row * 12;
        cp_async16(sQ + row * QPITCH + dc * 16,
                   qkv + (size_t)(b * Ss + qb + row) * QKVS + h * DHd + dc * 8, 16);
    }
    CP_COMMIT();

    auto load_kv = [&](int jt, int s) {
        #pragma unroll
        for (int i = 0; i < 3; ++i) {
            int c = tid + 256 * i;
            int kv = (c >= 384) ? 1 : 0;
            int cc = c - kv * 384;
            int row = cc / 12, dc = cc - row * 12;
            cp_async16(sKV + s * 13312 + kv * 6656 + row * QPITCH + dc * 16,
                       qkv + (size_t)(b * Ss + jt + row) * QKVS + (1 + kv) * Dd
                           + h * DHd + dc * 8, 16);
        }
        CP_COMMIT();
    };

    const int ntiles  = (qb + 128) / 32;
    load_kv(0, 0);
    load_kv(32, 1);
    CP_WAIT(2);
    __syncthreads();

    uint32_t qf[6][4];
    {
        uint32_t base = sQ + (wid * 16 + (lane & 15)) * QPITCH + ((lane >> 4) << 3) * 2;
        #pragma unroll
        for (int ks = 0; ks < 6; ++ks)
            ldm_x4(qf[ks], base + ks * 32);
    }

    float oacc[12][4];
    #pragma unroll
    for (int i = 0; i < 12; ++i)
        #pragma unroll
        for (int r = 0; r < 4; ++r) oacc[i][r] = 0.f;
    float m0 = -1e30f, m1 = -1e30f, l0 = 0.f, l1 = 0.f;

    const int my_last = qb + wid * 16 + 15;
    const int r0g     = qb + wid * 16 + (lane >> 2);

    for (int t = 0; t < ntiles; ++t) {
        const int jt = t * 32;
        if (t + 1 < ntiles) { CP_WAIT(1); } else { CP_WAIT(0); }
        __syncthreads();
        if (t + 2 < ntiles) load_kv((t + 2) * 32, (t + 2) % 3);

        if (jt <= my_last) {
            const uint32_t kb = sKV + (t % 3) * 13312;
            const uint32_t vb = kb + 6656;

            float sacc[4][4];
            #pragma unroll
            for (int i = 0; i < 4; ++i)
                #pragma unroll
                for (int r = 0; r < 4; ++r) sacc[i][r] = 0.f;
            const uint32_t kbase = kb + ((lane & 7) + ((lane >> 4) << 3)) * QPITCH
                                 + (((lane >> 3) & 1) << 4);
            #pragma unroll
            for (int ks = 0; ks < 6; ++ks) {
                uint32_t kf[4], kg[4];
                ldm_x4(kf, kbase + ks * 32);
                ldm_x4(kg, kbase + 16 * QPITCH + ks * 32);
                mma16816(sacc[0], qf[ks], &kf[0]);
                mma16816(sacc[1], qf[ks], &kf[2]);
                mma16816(sacc[2], qf[ks], &kg[0]);
                mma16816(sacc[3], qf[ks], &kg[2]);
            }

            #pragma unroll
            for (int nb = 0; nb < 4; ++nb)
                #pragma unroll
                for (int e = 0; e < 4; ++e) {
                    int j = jt + nb * 8 + (lane & 3) * 2 + (e & 1);
                    int r = r0g + ((e >> 1) << 3);
                    float v = sacc[nb][e] * scale2;
                    sacc[nb][e] = (j <= r) ? v : -1e30f;
                }

            float mx0 = -1e30f, mx1 = -1e30f;
            #pragma unroll
            for (int nb = 0; nb < 4; ++nb) {
                mx0 = fmaxf(mx0, fmaxf(sacc[nb][0], sacc[nb][1]));
                mx1 = fmaxf(mx1, fmaxf(sacc[nb][2], sacc[nb][3]));
            }
            mx0 = fmaxf(mx0, __shfl_xor_sync(0xffffffffu, mx0, 1));
            mx0 = fmaxf(mx0, __shfl_xor_sync(0xffffffffu, mx0, 2));
            mx1 = fmaxf(mx1, __shfl_xor_sync(0xffffffffu, mx1, 1));
            mx1 = fmaxf(mx1, __shfl_xor_sync(0xffffffffu, mx1, 2));
            float mn0 = fmaxf(m0, mx0), mn1 = fmaxf(m1, mx1);

            if (__any_sync(0xffffffffu, (mn0 > m0) || (mn1 > m1))) {
                float f0 = ex2(m0 - mn0), f1 = ex2(m1 - mn1);
                l0 *= f0; l1 *= f1;
                #pragma unroll
                for (int c6 = 0; c6 < 12; ++c6) {
                    oacc[c6][0] *= f0; oacc[c6][1] *= f0;
                    oacc[c6][2] *= f1; oacc[c6][3] *= f1;
                }
            }
            m0 = mn0; m1 = mn1;

            float s0 = 0.f, s1 = 0.f;
            #pragma unroll
            for (int nb = 0; nb < 4; ++nb) {
                float p0 = ex2(sacc[nb][0] - mn0);
                float p1 = ex2(sacc[nb][1] - mn0);
                float p2 = ex2(sacc[nb][2] - mn1);
                float p3 = ex2(sacc[nb][3] - mn1);
                sacc[nb][0] = p0; sacc[nb][1] = p1;
                sacc[nb][2] = p2; sacc[nb][3] = p3;
                s0 += p0 + p1; s1 += p2 + p3;
            }
            s0 += __shfl_xor_sync(0xffffffffu, s0, 1);
            s0 += __shfl_xor_sync(0xffffffffu, s0, 2);
            s1 += __shfl_xor_sync(0xffffffffu, s1, 1);
            s1 += __shfl_xor_sync(0xffffffffu, s1, 2);
            l0 += s0;
            l1 += s1;

            uint32_t pa[2][4];
            #pragma unroll
            for (int kk = 0; kk < 2; ++kk) {
                pa[kk][0] = pack_h2(sacc[kk*2][0],   sacc[kk*2][1]);
                pa[kk][1] = pack_h2(sacc[kk*2][2],   sacc[kk*2][3]);
                pa[kk][2] = pack_h2(sacc[kk*2+1][0], sacc[kk*2+1][1]);
                pa[kk][3] = pack_h2(sacc[kk*2+1][2], sacc[kk*2+1][3]);
            }

            const uint32_t vrow = vb + ((lane & 7) + (((lane >> 3) & 1) << 3)) * QPITCH;
            #pragma unroll
            for (int kk = 0; kk < 2; ++kk) {
                #pragma unroll
                for (int c6 = 0; c6 < 6; ++c6) {
                    uint32_t vf[4];
                    ldm_trans_x4(vf, vrow + kk * 16 * QPITCH
                                     + (c6 * 16 + ((lane >> 4) << 3)) * 2);
                    mma16816(oacc[c6 * 2],     pa[kk], &vf[0]);
                    mma16816(oacc[c6 * 2 + 1], pa[kk], &vf[2]);
                }
            }
        }
    }

    float il0 = 1.f / l0, il1 = 1.f / l1;
    #pragma unroll
    for (int c6 = 0; c6 < 12; ++c6) {
        int col = h * DHd + c6 * 8 + (lane & 3) * 2;
        *(__half2*)(o16 + (size_t)(b * Ss + r0g) * Dd + col) =
            __floats2half2_rn(oacc[c6][0] * il0, oacc[c6][1] * il0);
        *(__half2*)(o16 + (size_t)(b * Ss + r0g + 8) * Dd + col) =
            __floats2half2_rn(oacc[c6][2] * il1, oacc[c6][3] * il1);
    }
}

// ================= launcher =================
extern "C" void kernel_launch(void* const* d_in, const int* in_sizes, int n_in,
                              void* d_out, int out_size)
{
    (void)in_sizes; (void)n_in; (void)out_size;
    const float* latent   = (const float*)d_in[0];
    const int*   target   = (const int*)  d_in[1];
    const float* tok_emb  = (const float*)d_in[2];
    const float* pos_emb  = (const float*)d_in[3];
    const float* sa_w_qkv = (const float*)d_in[4];
    const float* sa_b_qkv = (const float*)d_in[5];
    const float* sa_w_o   = (const float*)d_in[6];
    const float* sa_b_o   = (const float*)d_in[7];
    const float* ca_w_qkv = (const float*)d_in[8];
    const float* ca_b_qkv = (const float*)d_in[9];
    const float* ca_w_o   = (const float*)d_in[10];
    const float* ca_b_o   = (const float*)d_in[11];
    const float* ffn_w1   = (const float*)d_in[12];
    const float* ffn_b1   = (const float*)d_in[13];
    const float* ffn_w2   = (const float*)d_in[14];
    const float* ffn_b2   = (const float*)d_in[15];
    const float* ln1_g    = (const float*)d_in[16];
    const float* ln1_b    = (const float*)d_in[17];
    const float* ln2_g    = (const float*)d_in[18];
    const float* ln2_b    = (const float*)d_in[19];
    const float* ln3_g    = (const float*)d_in[20];
    const float* ln3_b    = (const float*)d_in[21];
    const float* out_w    = (const float*)d_in[22];
    const float* out_b    = (const float*)d_in[23];

    float *x, *cat, *ca, *part;
    __half *x16, *o16, *y16, *h16, *qkv16, *wqkv16, *wo16, *w116, *w216, *wout16;
    cudaGetSymbolAddress((void**)&x,    g_x);
    cudaGetSymbolAddress((void**)&cat,  g_cat);
    cudaGetSymbolAddress((void**)&ca,   g_ca);
    cudaGetSymbolAddress((void**)&part, g_part);
    cudaGetSymbolAddress((void**)&x16,  g_x16);
    cudaGetSymbolAddress((void**)&o16,  g_o16);
    cudaGetSymbolAddress((void**)&y16,  g_y16);
    cudaGetSymbolAddress((void**)&h16,  g_h16);
    cudaGetSymbolAddress((void**)&qkv16, g_qkv16);
    cudaGetSymbolAddress((void**)&wqkv16, g_wqkv16);
    cudaGetSymbolAddress((void**)&wo16,   g_wo16);
    cudaGetSymbolAddress((void**)&w116,   g_w116);
    cudaGetSymbolAddress((void**)&w216,   g_w216);
    cudaGetSymbolAddress((void**)&wout16, g_wout16);

    cudaFuncSetAttribute(gemm_fp16,    cudaFuncAttributeMaxDynamicSharedMemorySize, GEMM_SMEM);
    cudaFuncSetAttribute(gemm_fp16_sk, cudaFuncAttributeMaxDynamicSharedMemorySize, GEMM_SMEM);
    cudaFuncSetAttribute(attn_flash,   cudaFuncAttributeMaxDynamicSharedMemorySize, FATT_SMEM);

    // 0: weight conversions (4096 floats per block)
    const int nb0 = (Ll*3*Dd*Dd) / 4096, nb1 = (Ll*Dd*Dd) / 4096,
              nb2 = (Ll*Ff*Dd) / 4096,   nb3 = (Ll*Dd*Ff) / 4096,
              nb4 = (Vv*Dd) / 4096;      // 76800/4096 = 18.75 -> handle remainder
    // Vv*Dd = 76800 = 18.75 * 4096; use 19 blocks and guard? 76800 = 4096*18 + 3072.
    // Use exact tiling: all sizes are multiples of 1024; use 1024-float blocks for tail array.
    convert_all<<<nb0 + nb1 + nb2 + nb3 + (Vv*Dd + 4095)/4096, 256>>>(
        sa_w_qkv, wqkv16, nb0, sa_w_o, wo16, nb1,
        ffn_w1, w116, nb2, ffn_w2, w216, nb3, out_w, wout16, (Vv*Dd + 4095)/4096);

    // 1: embed (vectorized)
    embed_kernel<<<Mm, 192>>>(target, tok_emb, pos_emb, x, x16);

    // 2: batched cross-attn stage-1
    const int SGB = (Ll * Bb * Dd) / 8;
    small_gemm_all<<<SGB, 256>>>(
        latent, 0,
        ca_w_qkv + (size_t)2*Dd*Dd, (size_t)3*Dd*Dd,
        ca_b_qkv + 2*Dd, 3*Dd, cat);

    // 3: QKV gemm (layer 0), 4: attention, 5: O-proj
    gemm_fp16<<<dim3(18, 64), 128, GEMM_SMEM>>>(
        x16, wqkv16, sa_b_qkv, nullptr, qkv16, Mm, QKVS, Dd, 2);
    attn_flash<<<512, 256, FATT_SMEM>>>(qkv16, o16);
    gemm_fp16<<<dim3(6, 64), 128, GEMM_SMEM>>>(
        o16, wo16, sa_b_o, nullptr, y16, Mm, Dd, Dd, 2);

    // 6: batched cross-attn stage-2
    small_gemm_all<<<SGB, 256>>>(
        cat, Bb*Dd,
        ca_w_o, (size_t)Dd*Dd,
        ca_b_o, Dd, ca);

    for (int l = 0; l < Ll; ++l) {
        if (l > 0) {
            gemm_fp16<<<dim3(18, 64), 128, GEMM_SMEM>>>(
                x16, wqkv16 + (size_t)l*3*Dd*Dd, sa_b_qkv + (size_t)l*3*Dd,
                nullptr, qkv16, Mm, QKVS, Dd, 2);
            attn_flash<<<512, 256, FATT_SMEM>>>(qkv16, o16);
            gemm_fp16<<<dim3(6, 64), 128, GEMM_SMEM>>>(
                o16, wo16 + (size_t)l*Dd*Dd, sa_b_o + (size_t)l*Dd,
                nullptr, y16, Mm, Dd, Dd, 2);
        }
        add_ln2_kernel<<<Mm/2, 256>>>(x, y16, ca + l*Bb*Dd,
                                      ln1_g + (size_t)l*Dd, ln1_b + (size_t)l*Dd,
                                      ln2_g + (size_t)l*Dd, ln2_b + (size_t)l*Dd, x16);
        gemm_fp16<<<dim3(16, 64), 128, GEMM_SMEM>>>(
            x16, w116 + (size_t)l*Ff*Dd, ffn_b1 + (size_t)l*Ff,
            nullptr, h16, Mm, Ff, Dd, 1);
        gemm_fp16<<<dim3(6, 64), 128, GEMM_SMEM>>>(
            h16, w216 + (size_t)l*Dd*Ff, ffn_b2 + (size_t)l*Dd,
            nullptr, y16, Mm, Dd, Ff, 2);
        add_ln_kernel<<<Mm/2, 256>>>(x, y16, ln3_g + (size_t)l*Dd, ln3_b + (size_t)l*Dd,
                                     x16);
    }

    // output projection: split-K x3 + reduce
    gemm_fp16_sk<<<dim3(1, 64, 3), 128, GEMM_SMEM>>>(
        x16, wout16, part, Mm, Vv, Dd/3, Dd);
    sk_reduce<<<(Mm*Vv + 255)/256, 256>>>(part, out_b, (float*)d_out);
}